// round 2
// baseline (speedup 1.0000x reference)
#include <cuda_runtime.h>
#include <math.h>

#define NS 1024
#define T  32
#define NF 16
#define H  192
#define G  768

// ---- static scratch (no allocs allowed) ----
static __device__ float g_gx0[(size_t)2*NS*T*G];
static __device__ float g_gx1[(size_t)NS*T*G];
static __device__ float g_gx1b[(size_t)NS*G];
static __device__ float g_h1[(size_t)NS*T*384];
static __device__ float g_h2[(size_t)NS*384];
static __device__ float g_BetaT[(size_t)NS*NS];
static __device__ float g_t3[NS*3];
static __device__ int   g_pid[NS];
static __device__ int   g_off[NS];
static __device__ float g_M[NS*128];
static __device__ float g_E[NS*128];
static __device__ float g_n1[NS*128];
static __device__ float g_n2[NS*128];

__device__ __forceinline__ float sigm(float x){ return 1.f/(1.f+expf(-x)); }

// ---- C[m][n] = sum_k A[m][k]*B[n][k] + bias0[n] + bias1[n]
// 128x128 tile, BK=16, 256 threads, 8x8 microtile.
__global__ __launch_bounds__(256,1)
void gemm_nt128(const float* __restrict__ A, int lda,
                const float* __restrict__ B, int ldb,
                float* __restrict__ C, int ldc, int K,
                const float* __restrict__ bias0, const float* __restrict__ bias1)
{
    __shared__ __align__(16) float As[16][136];
    __shared__ __align__(16) float Bs[16][136];
    const int m0 = blockIdx.x*128, n0 = blockIdx.y*128;
    const int tid = threadIdx.x;
    const int ty = tid>>4, tx = tid&15;
    const int row = tid>>1, kq = (tid&1)*8;
    float acc[8][8];
    #pragma unroll
    for (int i=0;i<8;i++)
        #pragma unroll
        for (int j=0;j<8;j++) acc[i][j]=0.f;

    for (int k0=0;k0<K;k0+=16){
        float4 a0 = *(const float4*)(A + (size_t)(m0+row)*lda + k0 + kq);
        float4 a1 = *(const float4*)(A + (size_t)(m0+row)*lda + k0 + kq + 4);
        float4 b0 = *(const float4*)(B + (size_t)(n0+row)*ldb + k0 + kq);
        float4 b1 = *(const float4*)(B + (size_t)(n0+row)*ldb + k0 + kq + 4);
        __syncthreads();
        As[kq+0][row]=a0.x; As[kq+1][row]=a0.y; As[kq+2][row]=a0.z; As[kq+3][row]=a0.w;
        As[kq+4][row]=a1.x; As[kq+5][row]=a1.y; As[kq+6][row]=a1.z; As[kq+7][row]=a1.w;
        Bs[kq+0][row]=b0.x; Bs[kq+1][row]=b0.y; Bs[kq+2][row]=b0.z; Bs[kq+3][row]=b0.w;
        Bs[kq+4][row]=b1.x; Bs[kq+5][row]=b1.y; Bs[kq+6][row]=b1.z; Bs[kq+7][row]=b1.w;
        __syncthreads();
        #pragma unroll
        for (int k=0;k<16;k++){
            float a[8], b[8];
            #pragma unroll
            for (int i=0;i<8;i++){ a[i]=As[k][ty*8+i]; b[i]=Bs[k][tx*8+i]; }
            #pragma unroll
            for (int i=0;i<8;i++)
                #pragma unroll
                for (int j=0;j<8;j++) acc[i][j] += a[i]*b[j];
        }
    }
    float bb[8];
    #pragma unroll
    for (int j=0;j<8;j++){
        int n = n0+tx*8+j;
        float v = 0.f;
        if (bias0) v += bias0[n];
        if (bias1) v += bias1[n];
        bb[j]=v;
    }
    #pragma unroll
    for (int i=0;i<8;i++){
        float* cp = C + (size_t)(m0+ty*8+i)*ldc + n0 + tx*8;
        #pragma unroll
        for (int j=0;j<8;j++) cp[j] = acc[i][j] + bb[j];
    }
}

// ---- C[m][n] = sum_k A[m][k]*B[k][n] (+addC[m][n]), 64x64 tile, 4x4 micro.
__global__ __launch_bounds__(256,1)
void gemm_nn64(const float* __restrict__ A, int lda,
               const float* __restrict__ B, int ldb,
               float* __restrict__ C, int ldc, int K,
               const float* __restrict__ addC)
{
    __shared__ __align__(16) float As[16][68];
    __shared__ __align__(16) float Bs[16][68];
    const int m0 = blockIdx.x*64, n0 = blockIdx.y*64;
    const int tid = threadIdx.x;
    const int ty = tid>>4, tx = tid&15;
    const int arow = tid>>2, akq = (tid&3)*4;
    const int bk = tid>>4, bnq = (tid&15)*4;
    float acc[4][4];
    #pragma unroll
    for (int i=0;i<4;i++)
        #pragma unroll
        for (int j=0;j<4;j++) acc[i][j]=0.f;

    for (int k0=0;k0<K;k0+=16){
        float4 av = *(const float4*)(A + (size_t)(m0+arow)*lda + k0 + akq);
        float4 bv = *(const float4*)(B + (size_t)(k0+bk)*ldb + n0 + bnq);
        __syncthreads();
        As[akq+0][arow]=av.x; As[akq+1][arow]=av.y; As[akq+2][arow]=av.z; As[akq+3][arow]=av.w;
        *(float4*)&Bs[bk][bnq] = bv;
        __syncthreads();
        #pragma unroll
        for (int k=0;k<16;k++){
            float a[4],b[4];
            #pragma unroll
            for (int i=0;i<4;i++){ a[i]=As[k][ty*4+i]; b[i]=Bs[k][tx*4+i]; }
            #pragma unroll
            for (int i=0;i<4;i++)
                #pragma unroll
                for (int j=0;j<4;j++) acc[i][j]+=a[i]*b[j];
        }
    }
    #pragma unroll
    for (int i=0;i<4;i++){
        int m = m0+ty*4+i;
        float* cp = C + (size_t)m*ldc + n0 + tx*4;
        const float* ap = addC ? addC + (size_t)m*ldc + n0 + tx*4 : (const float*)0;
        #pragma unroll
        for (int j=0;j<4;j++){
            float v = acc[i][j];
            if (ap) v += ap[j];
            cp[j] = v;
        }
    }
}

// ---- fused LSTM recurrence: 16 stocks/block, 32 steps internal.
// gates = gx[s][tt][768] + h @ Whh^T
// mode 0: L0 fwd -> h1[s][tt][0:192]; mode 1: L0 bwd -> h1[s][tt][192:384], tt=31-step
// mode 2: L1 fwd -> h2[s][0:192] at last step only.
__global__ __launch_bounds__(256,1)
void lstm_rec(const float* __restrict__ gx, const float* __restrict__ Whh,
              float* __restrict__ outp, int mode)
{
    extern __shared__ float sm[];
    float* Bsh = sm;              // [192][196]
    float* Hs  = sm + 192*196;    // [16][196]

    const int tid = threadIdx.x;
    const int jg = tid >> 2;      // 0..63 -> units jg*3 + {0,1,2}
    const int sg = tid & 3;       // 0..3  -> stocks sg*4 + {0..3}
    const int s0 = blockIdx.x * 16;

    for (int i = tid; i < 16*196; i += 256) Hs[i] = 0.f;
    __syncthreads();

    float c[4][3];
    #pragma unroll
    for (int a=0;a<4;a++)
        #pragma unroll
        for (int b=0;b<3;b++) c[a][b]=0.f;

    float acc[4][4][3];

    for (int step=0; step<T; ++step){
        const int tt = (mode==1) ? (T-1-step) : step;
        #pragma unroll
        for (int ss=0;ss<4;ss++){
            const float* gp = gx + ((size_t)(s0 + sg*4 + ss)*T + tt)*G;
            #pragma unroll
            for (int q=0;q<4;q++)
                #pragma unroll
                for (int jj=0;jj<3;jj++)
                    acc[q][ss][jj] = gp[q*H + jg*3 + jj];
        }
        #pragma unroll
        for (int q=0;q<4;q++){
            __syncthreads();
            const float* Wq = Whh + (size_t)q*H*H;
            for (int i = tid; i < 192*48; i += 256){
                int r = i / 48, cq = i % 48;
                float4 v = *(const float4*)(Wq + (size_t)r*H + cq*4);
                *(float4*)(Bsh + r*196 + cq*4) = v;
            }
            __syncthreads();
            #pragma unroll 2
            for (int k=0;k<192;k+=4){
                float4 b0 = *(const float4*)(Bsh + (jg*3+0)*196 + k);
                float4 b1 = *(const float4*)(Bsh + (jg*3+1)*196 + k);
                float4 b2 = *(const float4*)(Bsh + (jg*3+2)*196 + k);
                #pragma unroll
                for (int ss=0;ss<4;ss++){
                    float4 hv = *(const float4*)(Hs + (sg*4+ss)*196 + k);
                    acc[q][ss][0] += hv.x*b0.x + hv.y*b0.y + hv.z*b0.z + hv.w*b0.w;
                    acc[q][ss][1] += hv.x*b1.x + hv.y*b1.y + hv.z*b1.z + hv.w*b1.w;
                    acc[q][ss][2] += hv.x*b2.x + hv.y*b2.y + hv.z*b2.z + hv.w*b2.w;
                }
            }
        }
        __syncthreads();
        #pragma unroll
        for (int ss=0;ss<4;ss++){
            #pragma unroll
            for (int jj=0;jj<3;jj++){
                float iv = sigm(acc[0][ss][jj]);
                float fv = sigm(acc[1][ss][jj]);
                float gv = tanhf(acc[2][ss][jj]);
                float ov = sigm(acc[3][ss][jj]);
                float cc = fv*c[ss][jj] + iv*gv;
                c[ss][jj] = cc;
                float hh = ov*tanhf(cc);
                int srow = sg*4+ss;
                int j = jg*3+jj;
                Hs[srow*196 + j] = hh;
                int s = s0 + srow;
                if (mode==0)        outp[((size_t)s*T+tt)*384 + j] = hh;
                else if (mode==1)   outp[((size_t)s*T+tt)*384 + 192 + j] = hh;
                else if (step==T-1) outp[(size_t)s*384 + j] = hh;
            }
        }
        __syncthreads();
    }
}

// ---- layer1 bwd @ t=31 only (h0=c0=0) ----
__global__ void bwd1_last(const float* __restrict__ gxb, float* __restrict__ h2)
{
    int n = blockIdx.x, j = threadIdx.x;
    const float* g = gxb + (size_t)n*G;
    float iv = sigm(g[j]);
    float gv = tanhf(g[2*H+j]);
    float ov = sigm(g[3*H+j]);
    float cc = iv*gv;
    h2[(size_t)n*384 + 192 + j] = ov*tanhf(cc);
}

// ---- dynamic network ----
__global__ void dyn_scalars(const float* __restrict__ x, const float* __restrict__ theta,
                            int* __restrict__ pid, int* __restrict__ off)
{
    int n = blockIdx.x*blockDim.x + threadIdx.x;
    if (n >= NS) return;
    float th  = theta[n];
    float x30 = x[((size_t)n*T + 30)*NF];
    float x31 = x[((size_t)n*T + 31)*NF];
    int p0 = (x30 > th) ? 1 : ((x30 < -th) ? -1 : 0);
    int p1 = (x31 > th) ? 1 : ((x31 < -th) ? -1 : 0);
    pid[n] = (p0+1)*3 + (p1+1);
    off[n] = (p1+1)*3;
}

__global__ __launch_bounds__(256,1)
void dyn_beta(const float* __restrict__ PP, const int* __restrict__ pid,
              const int* __restrict__ off, float* __restrict__ BetaT,
              float* __restrict__ t3)
{
    __shared__ float s_raw[1024];
    __shared__ float s_adj[1024*3];
    __shared__ float s_red[256];
    const int y = blockIdx.x, tid = threadIdx.x;
    const int offy = off[y];
    for (int x=tid; x<NS; x+=256){
        size_t base = ((size_t)x*NS + y)*81 + (size_t)pid[x]*9 + offy;
        float a0=PP[base], a1=PP[base+1], a2=PP[base+2];
        s_adj[x*3+0]=a0; s_adj[x*3+1]=a1; s_adj[x*3+2]=a2;
        float nr = sqrtf(a0*a0+a1*a1+a2*a2);
        s_raw[x] = (nr > 0.38f) ? nr : 0.f;
    }
    __syncthreads();
    float lm = -1e30f;
    for (int x=tid; x<NS; x+=256) lm = fmaxf(lm, s_raw[x]);
    s_red[tid]=lm; __syncthreads();
    for (int o=128;o>0;o>>=1){ if(tid<o) s_red[tid]=fmaxf(s_red[tid],s_red[tid+o]); __syncthreads(); }
    const float mx = s_red[0];
    __syncthreads();
    float ls = 0.f;
    for (int x=tid; x<NS; x+=256){ float e=expf(s_raw[x]-mx); s_raw[x]=e; ls+=e; }
    s_red[tid]=ls; __syncthreads();
    for (int o=128;o>0;o>>=1){ if(tid<o) s_red[tid]+=s_red[tid+o]; __syncthreads(); }
    const float inv = 1.f/s_red[0];
    __syncthreads();
    float t0=0.f,t1=0.f,t2=0.f;
    for (int x=tid; x<NS; x+=256){
        float b = s_raw[x]*inv;
        BetaT[(size_t)y*NS + x] = b;
        t0 += b*s_adj[x*3+0]; t1 += b*s_adj[x*3+1]; t2 += b*s_adj[x*3+2];
    }
    s_red[tid]=t0; __syncthreads();
    for (int o=128;o>0;o>>=1){ if(tid<o) s_red[tid]+=s_red[tid+o]; __syncthreads(); }
    if(tid==0) t3[y*3+0]=s_red[0];
    __syncthreads();
    s_red[tid]=t1; __syncthreads();
    for (int o=128;o>0;o>>=1){ if(tid<o) s_red[tid]+=s_red[tid+o]; __syncthreads(); }
    if(tid==0) t3[y*3+1]=s_red[0];
    __syncthreads();
    s_red[tid]=t2; __syncthreads();
    for (int o=128;o>0;o>>=1){ if(tid<o) s_red[tid]+=s_red[tid+o]; __syncthreads(); }
    if(tid==0) t3[y*3+2]=s_red[0];
}

// ---- E[y][u] = t3[y][:] . Wa[:,u] + b[u] ----
__global__ void agg_extra(const float* __restrict__ t3, const float* __restrict__ Wa,
                          const float* __restrict__ b, float* __restrict__ E)
{
    int y = blockIdx.x, u = threadIdx.x;
    float v = b[u] + t3[y*3+0]*Wa[u] + t3[y*3+1]*Wa[128+u] + t3[y*3+2]*Wa[256+u];
    E[(size_t)y*128 + u] = v;
}

// ---- final projection + tanh ----
__global__ void out_kernel(const float* __restrict__ nfeat, const float* __restrict__ n1,
                           const float* __restrict__ n2, const float* __restrict__ W,
                           const float* __restrict__ b, float* __restrict__ out)
{
    int idx = blockIdx.x*blockDim.x + threadIdx.x;
    if (idx >= NS*2) return;
    int n = idx >> 1, o = idx & 1;
    float s = b[o];
    for (int k=0;k<384;k++) s += nfeat[(size_t)n*384+k]*W[k*2+o];
    for (int k=0;k<128;k++) s += n1[(size_t)n*128+k]*W[(384+k)*2+o];
    for (int k=0;k<128;k++) s += n2[(size_t)n*128+k]*W[(512+k)*2+o];
    out[idx] = tanhf(s);
}

extern "C" void kernel_launch(void* const* d_in, const int* in_sizes, int n_in,
                              void* d_out, int out_size)
{
    const float* x     = (const float*)d_in[0];
    const float* theta = (const float*)d_in[1];
    const float* PP    = (const float*)d_in[2];
    const float* Wih0  = (const float*)d_in[3];
    const float* Whh0  = (const float*)d_in[4];
    const float* bih0  = (const float*)d_in[5];
    const float* bhh0  = (const float*)d_in[6];
    const float* Wih1  = (const float*)d_in[7];
    const float* Whh1  = (const float*)d_in[8];
    const float* bih1  = (const float*)d_in[9];
    const float* bhh1  = (const float*)d_in[10];
    const float* Wagg1 = (const float*)d_in[11];
    const float* bagg1 = (const float*)d_in[12];
    const float* Wagg2 = (const float*)d_in[13];
    const float* bagg2 = (const float*)d_in[14];
    const float* Wout  = (const float*)d_in[15];
    const float* bout  = (const float*)d_in[16];
    float* out = (float*)d_out;

    float *p_gx0, *p_gx1, *p_gx1b, *p_h1, *p_h2, *p_BetaT, *p_t3, *p_M, *p_E, *p_n1, *p_n2;
    int *p_pid, *p_off;
    cudaGetSymbolAddress((void**)&p_gx0,  g_gx0);
    cudaGetSymbolAddress((void**)&p_gx1,  g_gx1);
    cudaGetSymbolAddress((void**)&p_gx1b, g_gx1b);
    cudaGetSymbolAddress((void**)&p_h1,   g_h1);
    cudaGetSymbolAddress((void**)&p_h2,   g_h2);
    cudaGetSymbolAddress((void**)&p_BetaT,g_BetaT);
    cudaGetSymbolAddress((void**)&p_t3,   g_t3);
    cudaGetSymbolAddress((void**)&p_pid,  g_pid);
    cudaGetSymbolAddress((void**)&p_off,  g_off);
    cudaGetSymbolAddress((void**)&p_M,    g_M);
    cudaGetSymbolAddress((void**)&p_E,    g_E);
    cudaGetSymbolAddress((void**)&p_n1,   g_n1);
    cudaGetSymbolAddress((void**)&p_n2,   g_n2);

    const int LSM = (192*196 + 16*196)*4;  // 163072 B
    cudaFuncSetAttribute(lstm_rec, cudaFuncAttributeMaxDynamicSharedMemorySize, LSM);

    // dynamic network (independent)
    dyn_scalars<<<4, 256>>>(x, theta, p_pid, p_off);
    dyn_beta<<<NS, 256>>>(PP, p_pid, p_off, p_BetaT, p_t3);

    // layer0 gx (both dirs): [32768,768] = x2d[32768,16] @ Wih0[d]^T + biases
    for (int d=0; d<2; d++){
        gemm_nt128<<<dim3(256,6), 256>>>(x, NF, Wih0 + (size_t)d*G*NF, NF,
                                         p_gx0 + (size_t)d*NS*T*G, G, NF,
                                         bih0 + d*G, bhh0 + d*G);
    }
    // layer0 recurrences
    lstm_rec<<<64, 256, LSM>>>(p_gx0,                 Whh0,                 p_h1, 0);
    lstm_rec<<<64, 256, LSM>>>(p_gx0 + (size_t)NS*T*G, Whh0 + (size_t)G*H,  p_h1, 1);

    // layer1 fwd gx: [32768,768] = h1[32768,384] @ Wih1[0]^T + biases
    gemm_nt128<<<dim3(256,6), 256>>>(p_h1, 384, Wih1, 384, p_gx1, G, 384,
                                     bih1, bhh1);
    // layer1 bwd gx at t=31 only: [1024,768] = h1[:,31,:] @ Wih1[1]^T + biases
    gemm_nt128<<<dim3(8,6), 256>>>(p_h1 + 31*384, T*384, Wih1 + (size_t)G*384, 384,
                                   p_gx1b, G, 384, bih1 + G, bhh1 + G);

    // layer1 recurrence fwd -> h2[:,0:192]; bwd single step -> h2[:,192:384]
    lstm_rec<<<64, 256, LSM>>>(p_gx1, Whh1, p_h2, 2);
    bwd1_last<<<NS, H>>>(p_gx1b, p_h2);

    // agg layer 1: M = h2 @ Wf1 ; n1 = BetaT @ M + (t3.Wa1 + b1)
    gemm_nn64<<<dim3(16,2), 256>>>(p_h2, 384, Wagg1, 128, p_M, 128, 384, (const float*)0);
    agg_extra<<<NS, 128>>>(p_t3, Wagg1 + (size_t)384*128, bagg1, p_E);
    gemm_nn64<<<dim3(16,2), 256>>>(p_BetaT, NS, p_M, 128, p_n1, 128, NS, p_E);

    // agg layer 2
    gemm_nn64<<<dim3(16,2), 256>>>(p_n1, 128, Wagg2, 128, p_M, 128, 128, (const float*)0);
    agg_extra<<<NS, 128>>>(p_t3, Wagg2 + (size_t)128*128, bagg2, p_E);
    gemm_nn64<<<dim3(16,2), 256>>>(p_BetaT, NS, p_M, 128, p_n2, 128, NS, p_E);

    // output
    out_kernel<<<8, 256>>>(p_h2, p_n1, p_n2, Wout, bout, out);
}

// round 3
// speedup vs baseline: 1.5732x; 1.5732x over previous
#include <cuda_runtime.h>
#include <math.h>

#define NS 1024
#define T  32
#define NF 16
#define H  192
#define G  768

typedef unsigned long long u64;

static __device__ float g_gx0[(size_t)2*NS*T*G];
static __device__ float g_gx1[(size_t)NS*T*G];
static __device__ float g_gx1b[(size_t)NS*G];
static __device__ float g_h1[(size_t)NS*T*384];
static __device__ float g_h2[(size_t)NS*384];
static __device__ float g_BetaT[(size_t)NS*NS];
static __device__ float g_t3[NS*3];
static __device__ int   g_pid[NS];
static __device__ int   g_off[NS];
static __device__ float g_M[NS*128];
static __device__ float g_E[NS*128];
static __device__ float g_n1[NS*128];
static __device__ float g_n2[NS*128];

__device__ __forceinline__ float sigm(float x){ return 1.f/(1.f+expf(-x)); }
__device__ __forceinline__ u64 pk(float x, float y){ u64 r; asm("mov.b64 %0,{%1,%2};":"=l"(r):"f"(x),"f"(y)); return r; }
__device__ __forceinline__ void fma2(u64& d, u64 a, u64 b){ asm("fma.rn.f32x2 %0,%1,%2,%0;":"+l"(d):"l"(a),"l"(b)); }
__device__ __forceinline__ float lohi(u64 v){ float x,y; asm("mov.b64 {%0,%1},%2;":"=f"(x),"=f"(y):"l"(v)); return x+y; }

// ---- C[m][n] = sum_k A[m][k]*B[n][k] + bias0[n] + bias1[n]
// 128x128 tile, BK=16, 256 threads, 8x8 microtile, f32x2 packed over k-pairs.
__global__ __launch_bounds__(256,1)
void gemm_nt128(const float* __restrict__ A, int lda,
                const float* __restrict__ B, int ldb,
                float* __restrict__ C, int ldc, int K,
                const float* __restrict__ bias0, const float* __restrict__ bias1)
{
    __shared__ __align__(16) float As[16][136];
    __shared__ __align__(16) float Bs[16][136];
    const int m0 = blockIdx.x*128, n0 = blockIdx.y*128;
    const int tid = threadIdx.x;
    const int ty = tid>>4, tx = tid&15;
    const int row = tid>>1, kq = (tid&1)*8;
    u64 acc[8][8];
    #pragma unroll
    for (int i=0;i<8;i++)
        #pragma unroll
        for (int j=0;j<8;j++) acc[i][j]=0ull;

    for (int k0=0;k0<K;k0+=16){
        float4 a0 = *(const float4*)(A + (size_t)(m0+row)*lda + k0 + kq);
        float4 a1 = *(const float4*)(A + (size_t)(m0+row)*lda + k0 + kq + 4);
        float4 b0 = *(const float4*)(B + (size_t)(n0+row)*ldb + k0 + kq);
        float4 b1 = *(const float4*)(B + (size_t)(n0+row)*ldb + k0 + kq + 4);
        __syncthreads();
        As[kq+0][row]=a0.x; As[kq+1][row]=a0.y; As[kq+2][row]=a0.z; As[kq+3][row]=a0.w;
        As[kq+4][row]=a1.x; As[kq+5][row]=a1.y; As[kq+6][row]=a1.z; As[kq+7][row]=a1.w;
        Bs[kq+0][row]=b0.x; Bs[kq+1][row]=b0.y; Bs[kq+2][row]=b0.z; Bs[kq+3][row]=b0.w;
        Bs[kq+4][row]=b1.x; Bs[kq+5][row]=b1.y; Bs[kq+6][row]=b1.z; Bs[kq+7][row]=b1.w;
        __syncthreads();
        #pragma unroll
        for (int k=0;k<16;k+=2){
            float4 aA = *(const float4*)&As[k][ty*8];
            float4 aB = *(const float4*)&As[k][ty*8+4];
            float4 aC = *(const float4*)&As[k+1][ty*8];
            float4 aD = *(const float4*)&As[k+1][ty*8+4];
            float4 bA = *(const float4*)&Bs[k][tx*8];
            float4 bB = *(const float4*)&Bs[k][tx*8+4];
            float4 bC = *(const float4*)&Bs[k+1][tx*8];
            float4 bD = *(const float4*)&Bs[k+1][tx*8+4];
            u64 aa[8], bb[8];
            aa[0]=pk(aA.x,aC.x); aa[1]=pk(aA.y,aC.y); aa[2]=pk(aA.z,aC.z); aa[3]=pk(aA.w,aC.w);
            aa[4]=pk(aB.x,aD.x); aa[5]=pk(aB.y,aD.y); aa[6]=pk(aB.z,aD.z); aa[7]=pk(aB.w,aD.w);
            bb[0]=pk(bA.x,bC.x); bb[1]=pk(bA.y,bC.y); bb[2]=pk(bA.z,bC.z); bb[3]=pk(bA.w,bC.w);
            bb[4]=pk(bB.x,bD.x); bb[5]=pk(bB.y,bD.y); bb[6]=pk(bB.z,bD.z); bb[7]=pk(bB.w,bD.w);
            #pragma unroll
            for (int i=0;i<8;i++)
                #pragma unroll
                for (int j=0;j<8;j++) fma2(acc[i][j], aa[i], bb[j]);
        }
    }
    float bv[8];
    #pragma unroll
    for (int j=0;j<8;j++){
        int n = n0+tx*8+j;
        float v = 0.f;
        if (bias0) v += bias0[n];
        if (bias1) v += bias1[n];
        bv[j]=v;
    }
    #pragma unroll
    for (int i=0;i<8;i++){
        float* cp = C + (size_t)(m0+ty*8+i)*ldc + n0 + tx*8;
        float4 o0, o1;
        o0.x = lohi(acc[i][0])+bv[0]; o0.y = lohi(acc[i][1])+bv[1];
        o0.z = lohi(acc[i][2])+bv[2]; o0.w = lohi(acc[i][3])+bv[3];
        o1.x = lohi(acc[i][4])+bv[4]; o1.y = lohi(acc[i][5])+bv[5];
        o1.z = lohi(acc[i][6])+bv[6]; o1.w = lohi(acc[i][7])+bv[7];
        *(float4*)cp = o0;
        *(float4*)(cp+4) = o1;
    }
}

// ---- C[m][n] = sum_k A[m][k]*B[k][n] (+addC), 64x64 tile, 4x4 micro.
__global__ __launch_bounds__(256,1)
void gemm_nn64(const float* __restrict__ A, int lda,
               const float* __restrict__ B, int ldb,
               float* __restrict__ C, int ldc, int K,
               const float* __restrict__ addC)
{
    __shared__ __align__(16) float As[16][68];
    __shared__ __align__(16) float Bs[16][68];
    const int m0 = blockIdx.x*64, n0 = blockIdx.y*64;
    const int tid = threadIdx.x;
    const int ty = tid>>4, tx = tid&15;
    const int arow = tid>>2, akq = (tid&3)*4;
    const int bk = tid>>4, bnq = (tid&15)*4;
    float acc[4][4];
    #pragma unroll
    for (int i=0;i<4;i++)
        #pragma unroll
        for (int j=0;j<4;j++) acc[i][j]=0.f;

    for (int k0=0;k0<K;k0+=16){
        float4 av = *(const float4*)(A + (size_t)(m0+arow)*lda + k0 + akq);
        float4 bv = *(const float4*)(B + (size_t)(k0+bk)*ldb + n0 + bnq);
        __syncthreads();
        As[akq+0][arow]=av.x; As[akq+1][arow]=av.y; As[akq+2][arow]=av.z; As[akq+3][arow]=av.w;
        *(float4*)&Bs[bk][bnq] = bv;
        __syncthreads();
        #pragma unroll
        for (int k=0;k<16;k++){
            float a[4],b[4];
            #pragma unroll
            for (int i=0;i<4;i++){ a[i]=As[k][ty*4+i]; b[i]=Bs[k][tx*4+i]; }
            #pragma unroll
            for (int i=0;i<4;i++)
                #pragma unroll
                for (int j=0;j<4;j++) acc[i][j]+=a[i]*b[j];
        }
    }
    #pragma unroll
    for (int i=0;i<4;i++){
        int m = m0+ty*4+i;
        float* cp = C + (size_t)m*ldc + n0 + tx*4;
        const float* ap = addC ? addC + (size_t)m*ldc + n0 + tx*4 : (const float*)0;
        #pragma unroll
        for (int j=0;j<4;j++){
            float v = acc[i][j];
            if (ap) v += ap[j];
            cp[j] = v;
        }
    }
}

// ---- fused LSTM recurrence v2: gate-interleaved, f32x2 packed.
// 16 stocks/block. Bsh[768 gate-rows][52] holds one 48-wide k-chunk of Whh.
// mode = mode0 + blockIdx.y. 0: L0 fwd; 1: L0 bwd (tt reversed, +192 out off);
// 2: L1 fwd (write h2 last step only).
__global__ __launch_bounds__(256,1)
void lstm_rec(const float* __restrict__ gx_all, const float* __restrict__ Whh_all,
              float* __restrict__ outp, int mode0)
{
    extern __shared__ float sm[];
    float* Bsh = sm;            // [768][52]
    float* Hs  = sm + 768*52;   // [16][196]
    const int dir = blockIdx.y;
    const int mode = mode0 + dir;
    const float* gx  = gx_all  + (size_t)dir*NS*T*G;
    const float* Whh = Whh_all + (size_t)dir*G*H;
    const int tid = threadIdx.x;
    const int jg = tid>>2;     // 0..63 -> units jg*3+{0,1,2}
    const int sg = tid&3;      // 0..3  -> stocks sg*4+{0..3}
    const int s0 = blockIdx.x*16;

    for (int i=tid;i<16*196;i+=256) Hs[i]=0.f;

    float c[4][3];
    #pragma unroll
    for (int a=0;a<4;a++)
        #pragma unroll
        for (int b=0;b<3;b++) c[a][b]=0.f;

    u64 acc[4][4][3];
    __syncthreads();

    for (int step=0; step<T; ++step){
        const int tt = (mode==1) ? (T-1-step) : step;
        // init acc from gx (global loads overlap staging below)
        #pragma unroll
        for (int ss=0;ss<4;ss++){
            const float* gp = gx + ((size_t)(s0+sg*4+ss)*T + tt)*G;
            #pragma unroll
            for (int q=0;q<4;q++)
                #pragma unroll
                for (int jj=0;jj<3;jj++)
                    acc[q][ss][jj] = pk(gp[q*H + jg*3 + jj], 0.f);
        }
        #pragma unroll 1
        for (int kb=0;kb<4;kb++){
            __syncthreads();
            #pragma unroll
            for (int it=0; it<36; it++){
                int idx = tid + it*256;      // 9216 = 768*12
                int gu = idx/12, k4 = idx - gu*12;
                float4 v = *(const float4*)(Whh + (size_t)gu*H + kb*48 + k4*4);
                *(float4*)(Bsh + gu*52 + k4*4) = v;
            }
            __syncthreads();
            #pragma unroll 2
            for (int k4=0;k4<12;k4++){
                const int kk = kb*48 + k4*4;
                u64 h01[4], h23[4];
                #pragma unroll
                for (int ss=0;ss<4;ss++){
                    float4 hv = *(const float4*)(Hs + (sg*4+ss)*196 + kk);
                    h01[ss]=pk(hv.x,hv.y); h23[ss]=pk(hv.z,hv.w);
                }
                #pragma unroll
                for (int q=0;q<4;q++){
                    u64 b01[3], b23[3];
                    #pragma unroll
                    for (int jj=0;jj<3;jj++){
                        float4 bv = *(const float4*)(Bsh + (q*192 + jg*3 + jj)*52 + k4*4);
                        b01[jj]=pk(bv.x,bv.y); b23[jj]=pk(bv.z,bv.w);
                    }
                    #pragma unroll
                    for (int ss=0;ss<4;ss++)
                        #pragma unroll
                        for (int jj=0;jj<3;jj++){
                            fma2(acc[q][ss][jj], h01[ss], b01[jj]);
                            fma2(acc[q][ss][jj], h23[ss], b23[jj]);
                        }
                }
            }
        }
        __syncthreads();   // all reads of old Hs done before overwrite
        #pragma unroll
        for (int ss=0;ss<4;ss++){
            #pragma unroll
            for (int jj=0;jj<3;jj++){
                float iv = sigm(lohi(acc[0][ss][jj]));
                float fv = sigm(lohi(acc[1][ss][jj]));
                float gv = tanhf(lohi(acc[2][ss][jj]));
                float ov = sigm(lohi(acc[3][ss][jj]));
                float cc = fv*c[ss][jj] + iv*gv;
                c[ss][jj] = cc;
                float hh = ov*tanhf(cc);
                int srow = sg*4+ss;
                int j = jg*3+jj;
                Hs[srow*196 + j] = hh;
                int s = s0 + srow;
                if (mode==0)        outp[((size_t)s*T+tt)*384 + j] = hh;
                else if (mode==1)   outp[((size_t)s*T+tt)*384 + 192 + j] = hh;
                else if (step==T-1) outp[(size_t)s*384 + j] = hh;
            }
        }
    }
}

// ---- layer1 bwd @ t=31 only (h0=c0=0) ----
__global__ void bwd1_last(const float* __restrict__ gxb, float* __restrict__ h2)
{
    int n = blockIdx.x, j = threadIdx.x;
    const float* g = gxb + (size_t)n*G;
    float iv = sigm(g[j]);
    float gv = tanhf(g[2*H+j]);
    float ov = sigm(g[3*H+j]);
    float cc = iv*gv;
    h2[(size_t)n*384 + 192 + j] = ov*tanhf(cc);
}

// ---- dynamic network ----
__global__ void dyn_scalars(const float* __restrict__ x, const float* __restrict__ theta,
                            int* __restrict__ pid, int* __restrict__ off)
{
    int n = blockIdx.x*blockDim.x + threadIdx.x;
    if (n >= NS) return;
    float th  = theta[n];
    float x30 = x[((size_t)n*T + 30)*NF];
    float x31 = x[((size_t)n*T + 31)*NF];
    int p0 = (x30 > th) ? 1 : ((x30 < -th) ? -1 : 0);
    int p1 = (x31 > th) ? 1 : ((x31 < -th) ? -1 : 0);
    pid[n] = (p0+1)*3 + (p1+1);
    off[n] = (p1+1)*3;
}

__global__ __launch_bounds__(256,1)
void dyn_beta(const float* __restrict__ PP, const int* __restrict__ pid,
              const int* __restrict__ off, float* __restrict__ BetaT,
              float* __restrict__ t3)
{
    __shared__ float s_raw[1024];
    __shared__ float s_adj[1024*3];
    __shared__ float s_red[256];
    const int y = blockIdx.x, tid = threadIdx.x;
    const int offy = off[y];
    for (int x=tid; x<NS; x+=256){
        size_t base = ((size_t)x*NS + y)*81 + (size_t)pid[x]*9 + offy;
        float a0=PP[base], a1=PP[base+1], a2=PP[base+2];
        s_adj[x*3+0]=a0; s_adj[x*3+1]=a1; s_adj[x*3+2]=a2;
        float nr = sqrtf(a0*a0+a1*a1+a2*a2);
        s_raw[x] = (nr > 0.38f) ? nr : 0.f;
    }
    __syncthreads();
    float lm = -1e30f;
    for (int x=tid; x<NS; x+=256) lm = fmaxf(lm, s_raw[x]);
    s_red[tid]=lm; __syncthreads();
    for (int o=128;o>0;o>>=1){ if(tid<o) s_red[tid]=fmaxf(s_red[tid],s_red[tid+o]); __syncthreads(); }
    const float mx = s_red[0];
    __syncthreads();
    float ls = 0.f;
    for (int x=tid; x<NS; x+=256){ float e=expf(s_raw[x]-mx); s_raw[x]=e; ls+=e; }
    s_red[tid]=ls; __syncthreads();
    for (int o=128;o>0;o>>=1){ if(tid<o) s_red[tid]+=s_red[tid+o]; __syncthreads(); }
    const float inv = 1.f/s_red[0];
    __syncthreads();
    float t0=0.f,t1=0.f,t2=0.f;
    for (int x=tid; x<NS; x+=256){
        float b = s_raw[x]*inv;
        BetaT[(size_t)y*NS + x] = b;
        t0 += b*s_adj[x*3+0]; t1 += b*s_adj[x*3+1]; t2 += b*s_adj[x*3+2];
    }
    s_red[tid]=t0; __syncthreads();
    for (int o=128;o>0;o>>=1){ if(tid<o) s_red[tid]+=s_red[tid+o]; __syncthreads(); }
    if(tid==0) t3[y*3+0]=s_red[0];
    __syncthreads();
    s_red[tid]=t1; __syncthreads();
    for (int o=128;o>0;o>>=1){ if(tid<o) s_red[tid]+=s_red[tid+o]; __syncthreads(); }
    if(tid==0) t3[y*3+1]=s_red[0];
    __syncthreads();
    s_red[tid]=t2; __syncthreads();
    for (int o=128;o>0;o>>=1){ if(tid<o) s_red[tid]+=s_red[tid+o]; __syncthreads(); }
    if(tid==0) t3[y*3+2]=s_red[0];
}

__global__ void agg_extra(const float* __restrict__ t3, const float* __restrict__ Wa,
                          const float* __restrict__ b, float* __restrict__ E)
{
    int y = blockIdx.x, u = threadIdx.x;
    float v = b[u] + t3[y*3+0]*Wa[u] + t3[y*3+1]*Wa[128+u] + t3[y*3+2]*Wa[256+u];
    E[(size_t)y*128 + u] = v;
}

// ---- final projection + tanh: warp per output ----
__global__ void out_kernel(const float* __restrict__ nfeat, const float* __restrict__ n1,
                           const float* __restrict__ n2, const float* __restrict__ W,
                           const float* __restrict__ b, float* __restrict__ out)
{
    int warp = (blockIdx.x*blockDim.x + threadIdx.x)>>5;
    int lane = threadIdx.x & 31;
    if (warp >= NS*2) return;
    int n = warp>>1, o = warp&1;
    float s = 0.f;
    for (int k=lane;k<384;k+=32) s += nfeat[(size_t)n*384+k]*W[k*2+o];
    for (int k=lane;k<128;k+=32) s += n1[(size_t)n*128+k]*W[(384+k)*2+o];
    for (int k=lane;k<128;k+=32) s += n2[(size_t)n*128+k]*W[(512+k)*2+o];
    #pragma unroll
    for (int m=16;m>0;m>>=1) s += __shfl_xor_sync(0xffffffffu, s, m);
    if (lane==0) out[warp] = tanhf(s + b[o]);
}

extern "C" void kernel_launch(void* const* d_in, const int* in_sizes, int n_in,
                              void* d_out, int out_size)
{
    const float* x     = (const float*)d_in[0];
    const float* theta = (const float*)d_in[1];
    const float* PP    = (const float*)d_in[2];
    const float* Wih0  = (const float*)d_in[3];
    const float* Whh0  = (const float*)d_in[4];
    const float* bih0  = (const float*)d_in[5];
    const float* bhh0  = (const float*)d_in[6];
    const float* Wih1  = (const float*)d_in[7];
    const float* Whh1  = (const float*)d_in[8];
    const float* bih1  = (const float*)d_in[9];
    const float* bhh1  = (const float*)d_in[10];
    const float* Wagg1 = (const float*)d_in[11];
    const float* bagg1 = (const float*)d_in[12];
    const float* Wagg2 = (const float*)d_in[13];
    const float* bagg2 = (const float*)d_in[14];
    const float* Wout  = (const float*)d_in[15];
    const float* bout  = (const float*)d_in[16];
    float* out = (float*)d_out;

    float *p_gx0, *p_gx1, *p_gx1b, *p_h1, *p_h2, *p_BetaT, *p_t3, *p_M, *p_E, *p_n1, *p_n2;
    int *p_pid, *p_off;
    cudaGetSymbolAddress((void**)&p_gx0,  g_gx0);
    cudaGetSymbolAddress((void**)&p_gx1,  g_gx1);
    cudaGetSymbolAddress((void**)&p_gx1b, g_gx1b);
    cudaGetSymbolAddress((void**)&p_h1,   g_h1);
    cudaGetSymbolAddress((void**)&p_h2,   g_h2);
    cudaGetSymbolAddress((void**)&p_BetaT,g_BetaT);
    cudaGetSymbolAddress((void**)&p_t3,   g_t3);
    cudaGetSymbolAddress((void**)&p_pid,  g_pid);
    cudaGetSymbolAddress((void**)&p_off,  g_off);
    cudaGetSymbolAddress((void**)&p_M,    g_M);
    cudaGetSymbolAddress((void**)&p_E,    g_E);
    cudaGetSymbolAddress((void**)&p_n1,   g_n1);
    cudaGetSymbolAddress((void**)&p_n2,   g_n2);

    const int LSM = (768*52 + 16*196)*4;   // 172288 B
    cudaFuncSetAttribute(lstm_rec, cudaFuncAttributeMaxDynamicSharedMemorySize, LSM);

    // dynamic network
    dyn_scalars<<<4, 256>>>(x, theta, p_pid, p_off);
    dyn_beta<<<NS, 256>>>(PP, p_pid, p_off, p_BetaT, p_t3);

    // layer0 gx (both dirs)
    for (int d=0; d<2; d++){
        gemm_nt128<<<dim3(256,6), 256>>>(x, NF, Wih0 + (size_t)d*G*NF, NF,
                                         p_gx0 + (size_t)d*NS*T*G, G, NF,
                                         bih0 + d*G, bhh0 + d*G);
    }
    // layer0 recurrence: fwd + bwd fused in one launch (128 blocks)
    lstm_rec<<<dim3(64,2), 256, LSM>>>(p_gx0, Whh0, p_h1, 0);

    // layer1 fwd gx
    gemm_nt128<<<dim3(256,6), 256>>>(p_h1, 384, Wih1, 384, p_gx1, G, 384,
                                     bih1, bhh1);
    // layer1 bwd gx at t=31 only
    gemm_nt128<<<dim3(8,6), 256>>>(p_h1 + 31*384, T*384, Wih1 + (size_t)G*384, 384,
                                   p_gx1b, G, 384, bih1 + G, bhh1 + G);

    // layer1 recurrence fwd; bwd single step
    lstm_rec<<<dim3(64,1), 256, LSM>>>(p_gx1, Whh1, p_h2, 2);
    bwd1_last<<<NS, H>>>(p_gx1b, p_h2);

    // agg layer 1
    gemm_nn64<<<dim3(16,2), 256>>>(p_h2, 384, Wagg1, 128, p_M, 128, 384, (const float*)0);
    agg_extra<<<NS, 128>>>(p_t3, Wagg1 + (size_t)384*128, bagg1, p_E);
    gemm_nn64<<<dim3(16,2), 256>>>(p_BetaT, NS, p_M, 128, p_n1, 128, NS, p_E);

    // agg layer 2
    gemm_nn64<<<dim3(16,2), 256>>>(p_n1, 128, Wagg2, 128, p_M, 128, 128, (const float*)0);
    agg_extra<<<NS, 128>>>(p_t3, Wagg2 + (size_t)128*128, bagg2, p_E);
    gemm_nn64<<<dim3(16,2), 256>>>(p_BetaT, NS, p_M, 128, p_n2, 128, NS, p_E);

    // output
    out_kernel<<<256, 256>>>(p_h2, p_n1, p_n2, Wout, bout, out);
}

// round 4
// speedup vs baseline: 1.8052x; 1.1475x over previous
#include <cuda_runtime.h>
#include <math.h>
#include <stdint.h>

#define NS 1024
#define T  32
#define NF 16
#define H  192
#define G  768

typedef unsigned long long u64;

static __device__ float g_gx0[(size_t)2*NS*T*G];
static __device__ float g_gx1[(size_t)NS*T*G];
static __device__ float g_gx1b[(size_t)NS*G];
static __device__ float g_h1[(size_t)NS*T*384];
static __device__ float g_h2[(size_t)NS*384];
static __device__ float g_BetaT[(size_t)NS*NS];
static __device__ float g_t3[NS*3];
static __device__ int   g_pid[NS];
static __device__ int   g_off[NS];
static __device__ float g_M[NS*128];
static __device__ float g_E[NS*128];
static __device__ float g_n1[NS*128];
static __device__ float g_n2[NS*128];

__device__ __forceinline__ float sigm(float x){ return 1.f/(1.f+expf(-x)); }
__device__ __forceinline__ u64 pk(float x, float y){ u64 r; asm("mov.b64 %0,{%1,%2};":"=l"(r):"f"(x),"f"(y)); return r; }
__device__ __forceinline__ void fma2(u64& d, u64 a, u64 b){ asm("fma.rn.f32x2 %0,%1,%2,%0;":"+l"(d):"l"(a),"l"(b)); }
__device__ __forceinline__ float lohi(u64 v){ float x,y; asm("mov.b64 {%0,%1},%2;":"=f"(x),"=f"(y):"l"(v)); return x+y; }
__device__ __forceinline__ uint32_t smem_u32(const void* p){
    uint32_t a; asm("{ .reg .u64 t; cvta.to.shared.u64 t, %1; cvt.u32.u64 %0, t; }":"=r"(a):"l"(p)); return a;
}
#define CL_ARRIVE() asm volatile("barrier.cluster.arrive.aligned;" ::: "memory")
#define CL_WAIT()   asm volatile("barrier.cluster.wait.aligned;"   ::: "memory")

// ---- C[m][n] = sum_k A[m][k]*B[n][k] + bias0[n] + bias1[n]
__global__ __launch_bounds__(256,1)
void gemm_nt128(const float* __restrict__ A, int lda,
                const float* __restrict__ B, int ldb,
                float* __restrict__ C, int ldc, int K,
                const float* __restrict__ bias0, const float* __restrict__ bias1)
{
    __shared__ __align__(16) float As[16][136];
    __shared__ __align__(16) float Bs[16][136];
    const int m0 = blockIdx.x*128, n0 = blockIdx.y*128;
    const int tid = threadIdx.x;
    const int ty = tid>>4, tx = tid&15;
    const int row = tid>>1, kq = (tid&1)*8;
    u64 acc[8][8];
    #pragma unroll
    for (int i=0;i<8;i++)
        #pragma unroll
        for (int j=0;j<8;j++) acc[i][j]=0ull;

    for (int k0=0;k0<K;k0+=16){
        float4 a0 = *(const float4*)(A + (size_t)(m0+row)*lda + k0 + kq);
        float4 a1 = *(const float4*)(A + (size_t)(m0+row)*lda + k0 + kq + 4);
        float4 b0 = *(const float4*)(B + (size_t)(n0+row)*ldb + k0 + kq);
        float4 b1 = *(const float4*)(B + (size_t)(n0+row)*ldb + k0 + kq + 4);
        __syncthreads();
        As[kq+0][row]=a0.x; As[kq+1][row]=a0.y; As[kq+2][row]=a0.z; As[kq+3][row]=a0.w;
        As[kq+4][row]=a1.x; As[kq+5][row]=a1.y; As[kq+6][row]=a1.z; As[kq+7][row]=a1.w;
        Bs[kq+0][row]=b0.x; Bs[kq+1][row]=b0.y; Bs[kq+2][row]=b0.z; Bs[kq+3][row]=b0.w;
        Bs[kq+4][row]=b1.x; Bs[kq+5][row]=b1.y; Bs[kq+6][row]=b1.z; Bs[kq+7][row]=b1.w;
        __syncthreads();
        #pragma unroll
        for (int k=0;k<16;k+=2){
            float4 aA = *(const float4*)&As[k][ty*8];
            float4 aB = *(const float4*)&As[k][ty*8+4];
            float4 aC = *(const float4*)&As[k+1][ty*8];
            float4 aD = *(const float4*)&As[k+1][ty*8+4];
            float4 bA = *(const float4*)&Bs[k][tx*8];
            float4 bB = *(const float4*)&Bs[k][tx*8+4];
            float4 bC = *(const float4*)&Bs[k+1][tx*8];
            float4 bD = *(const float4*)&Bs[k+1][tx*8+4];
            u64 aa[8], bb[8];
            aa[0]=pk(aA.x,aC.x); aa[1]=pk(aA.y,aC.y); aa[2]=pk(aA.z,aC.z); aa[3]=pk(aA.w,aC.w);
            aa[4]=pk(aB.x,aD.x); aa[5]=pk(aB.y,aD.y); aa[6]=pk(aB.z,aD.z); aa[7]=pk(aB.w,aD.w);
            bb[0]=pk(bA.x,bC.x); bb[1]=pk(bA.y,bC.y); bb[2]=pk(bA.z,bC.z); bb[3]=pk(bA.w,bC.w);
            bb[4]=pk(bB.x,bD.x); bb[5]=pk(bB.y,bD.y); bb[6]=pk(bB.z,bD.z); bb[7]=pk(bB.w,bD.w);
            #pragma unroll
            for (int i=0;i<8;i++)
                #pragma unroll
                for (int j=0;j<8;j++) fma2(acc[i][j], aa[i], bb[j]);
        }
    }
    float bv[8];
    #pragma unroll
    for (int j=0;j<8;j++){
        int n = n0+tx*8+j;
        float v = 0.f;
        if (bias0) v += bias0[n];
        if (bias1) v += bias1[n];
        bv[j]=v;
    }
    #pragma unroll
    for (int i=0;i<8;i++){
        float* cp = C + (size_t)(m0+ty*8+i)*ldc + n0 + tx*8;
        float4 o0, o1;
        o0.x = lohi(acc[i][0])+bv[0]; o0.y = lohi(acc[i][1])+bv[1];
        o0.z = lohi(acc[i][2])+bv[2]; o0.w = lohi(acc[i][3])+bv[3];
        o1.x = lohi(acc[i][4])+bv[4]; o1.y = lohi(acc[i][5])+bv[5];
        o1.z = lohi(acc[i][6])+bv[6]; o1.w = lohi(acc[i][7])+bv[7];
        *(float4*)cp = o0;
        *(float4*)(cp+4) = o1;
    }
}

// ---- C[m][n] = sum_k A[m][k]*B[k][n] (+addC), 64x64 tile, 4x4 micro.
__global__ __launch_bounds__(256,1)
void gemm_nn64(const float* __restrict__ A, int lda,
               const float* __restrict__ B, int ldb,
               float* __restrict__ C, int ldc, int K,
               const float* __restrict__ addC)
{
    __shared__ __align__(16) float As[16][68];
    __shared__ __align__(16) float Bs[16][68];
    const int m0 = blockIdx.x*64, n0 = blockIdx.y*64;
    const int tid = threadIdx.x;
    const int ty = tid>>4, tx = tid&15;
    const int arow = tid>>2, akq = (tid&3)*4;
    const int bk = tid>>4, bnq = (tid&15)*4;
    float acc[4][4];
    #pragma unroll
    for (int i=0;i<4;i++)
        #pragma unroll
        for (int j=0;j<4;j++) acc[i][j]=0.f;

    for (int k0=0;k0<K;k0+=16){
        float4 av = *(const float4*)(A + (size_t)(m0+arow)*lda + k0 + akq);
        float4 bv = *(const float4*)(B + (size_t)(k0+bk)*ldb + n0 + bnq);
        __syncthreads();
        As[akq+0][arow]=av.x; As[akq+1][arow]=av.y; As[akq+2][arow]=av.z; As[akq+3][arow]=av.w;
        *(float4*)&Bs[bk][bnq] = bv;
        __syncthreads();
        #pragma unroll
        for (int k=0;k<16;k++){
            float a[4],b[4];
            #pragma unroll
            for (int i=0;i<4;i++){ a[i]=As[k][ty*4+i]; b[i]=Bs[k][tx*4+i]; }
            #pragma unroll
            for (int i=0;i<4;i++)
                #pragma unroll
                for (int j=0;j<4;j++) acc[i][j]+=a[i]*b[j];
        }
    }
    #pragma unroll
    for (int i=0;i<4;i++){
        int m = m0+ty*4+i;
        float* cp = C + (size_t)m*ldc + n0 + tx*4;
        const float* ap = addC ? addC + (size_t)m*ldc + n0 + tx*4 : (const float*)0;
        #pragma unroll
        for (int j=0;j<4;j++){
            float v = acc[i][j];
            if (ap) v += ap[j];
            cp[j] = v;
        }
    }
}

// ---- cluster LSTM recurrence: Whh resident in smem across all 32 steps.
// Cluster of 4 CTAs; CTA rank r holds gate-unit slice j in [r*48, r*48+48)
// for all 4 gates (192 rows x 192 k = 147KB). Cluster handles SPC stocks.
// h (full 192 units x SPC stocks) replicated in each CTA's Hs; after each
// step every CTA pushes its 48-unit h slice to all peers via DSMEM.
// mode = mode0 + blockIdx.y: 0=L0 fwd, 1=L0 bwd (tt reversed, +192 out),
// 2=L1 fwd (write h2 at last step only).
template<int SPC>
__global__ __launch_bounds__(256,1) __cluster_dims__(4,1,1)
void lstm_cluster(const float* __restrict__ gx_all, const float* __restrict__ Whh_all,
                  float* __restrict__ outp, int mode0)
{
    constexpr int SPT = SPC/16;        // stocks per thread
    constexpr int HSP = 202;           // Hs row stride (floats)
    constexpr int BSP = 196;           // Bsh row stride
    extern __shared__ float sm[];
    float* Bsh = sm;                   // [192][BSP]
    float* Hs  = sm + 192*BSP;         // [SPC][HSP]

    const int dir  = blockIdx.y;
    const int mode = mode0 + dir;
    const float* gx  = gx_all  + (size_t)dir*NS*T*G;
    const float* Whh = Whh_all + (size_t)dir*G*H;

    const int tid  = threadIdx.x;
    const int sgrp = tid & 15;         // stocks sgrp + 16*ss
    const int rgrp = tid >> 4;         // units rgrp*3 + {0,1,2}
    uint32_t rank; asm("mov.u32 %0, %%cluster_ctarank;" : "=r"(rank));
    const int cid   = blockIdx.x >> 2;
    const int sbase = cid * SPC;
    const int jsl   = (int)rank * 48;
    const uint32_t hs_base = smem_u32(Hs);

    // stage Whh slice once: local row lr = q*48+u  <-  global row q*192+jsl+u
    for (int i = tid; i < 192*48; i += 256){
        int lr = i / 48, c4 = i % 48;
        int q = lr / 48, u = lr % 48;
        float4 v = *(const float4*)(Whh + (size_t)(q*192 + jsl + u)*H + c4*4);
        *(float4*)(Bsh + lr*BSP + c4*4) = v;
    }
    for (int i = tid; i < SPC*HSP; i += 256) Hs[i] = 0.f;
    CL_ARRIVE(); CL_WAIT();

    float c[3][SPT];
    #pragma unroll
    for (int a=0;a<3;a++)
        #pragma unroll
        for (int b=0;b<SPT;b++) c[a][b]=0.f;

    for (int step=0; step<T; ++step){
        const int tt = (mode==1) ? (T-1-step) : step;
        u64 acc[3][4][SPT];
        #pragma unroll
        for (int uu=0;uu<3;uu++)
            #pragma unroll
            for (int q=0;q<4;q++)
                #pragma unroll
                for (int ss=0;ss<SPT;ss++) acc[uu][q][ss]=0ull;

        #pragma unroll 1
        for (int k=0;k<192;k+=4){
            u64 h0[SPT], h1[SPT];
            #pragma unroll
            for (int ss=0;ss<SPT;ss++){
                const float* hp = Hs + (sgrp + 16*ss)*HSP + k;
                h0[ss] = *(const u64*)hp;
                h1[ss] = *(const u64*)(hp+2);
            }
            #pragma unroll
            for (int uu=0;uu<3;uu++)
                #pragma unroll
                for (int q=0;q<4;q++){
                    const float* bp = Bsh + (q*48 + rgrp*3 + uu)*BSP + k;
                    ulonglong2 bv = *(const ulonglong2*)bp;
                    #pragma unroll
                    for (int ss=0;ss<SPT;ss++){
                        fma2(acc[uu][q][ss], h0[ss], bv.x);
                        fma2(acc[uu][q][ss], h1[ss], bv.y);
                    }
                }
        }
        // fold accumulators to scalars (frees half the regs)
        float pre[3][4][SPT];
        #pragma unroll
        for (int uu=0;uu<3;uu++)
            #pragma unroll
            for (int q=0;q<4;q++)
                #pragma unroll
                for (int ss=0;ss<SPT;ss++) pre[uu][q][ss] = lohi(acc[uu][q][ss]);

        CL_ARRIVE();                       // my reads of Hs(t-1) are done
        // add gx while peers drain (global loads hidden behind barrier)
        #pragma unroll
        for (int ss=0;ss<SPT;ss++){
            const float* gp = gx + ((size_t)(sbase + sgrp + 16*ss)*T + tt)*G;
            #pragma unroll
            for (int uu=0;uu<3;uu++)
                #pragma unroll
                for (int q=0;q<4;q++)
                    pre[uu][q][ss] += gp[q*192 + jsl + rgrp*3 + uu];
        }
        CL_WAIT();                         // everyone's reads done -> safe to write

        float hv[3][SPT];
        #pragma unroll
        for (int uu=0;uu<3;uu++)
            #pragma unroll
            for (int ss=0;ss<SPT;ss++){
                float iv = sigm(pre[uu][0][ss]);
                float fv = sigm(pre[uu][1][ss]);
                float gv = tanhf(pre[uu][2][ss]);
                float ov = sigm(pre[uu][3][ss]);
                float cc = fv*c[uu][ss] + iv*gv;
                c[uu][ss] = cc;
                hv[uu][ss] = ov*tanhf(cc);
            }
        // push h slice to all 4 CTAs (incl. self)
        #pragma unroll
        for (int ss=0;ss<SPT;ss++){
            int sl = sgrp + 16*ss;
            #pragma unroll
            for (int uu=0;uu<3;uu++){
                uint32_t la = hs_base + (uint32_t)(sl*HSP + jsl + rgrp*3 + uu)*4u;
                float v = hv[uu][ss];
                #pragma unroll
                for (int r=0;r<4;r++){
                    uint32_t da; asm("mapa.shared::cluster.u32 %0,%1,%2;":"=r"(da):"r"(la),"r"(r));
                    asm volatile("st.shared::cluster.f32 [%0],%1;"::"r"(da),"f"(v));
                }
            }
        }
        CL_ARRIVE();                       // release h(t) writes
        // global output stores hidden behind the wait
        if (mode==0 || mode==1){
            #pragma unroll
            for (int ss=0;ss<SPT;ss++){
                int s = sbase + sgrp + 16*ss;
                float* op = outp + ((size_t)s*T + tt)*384 + (mode==1?192:0) + jsl + rgrp*3;
                op[0]=hv[0][ss]; op[1]=hv[1][ss]; op[2]=hv[2][ss];
            }
        } else if (step==T-1){
            #pragma unroll
            for (int ss=0;ss<SPT;ss++){
                int s = sbase + sgrp + 16*ss;
                float* op = outp + (size_t)s*384 + jsl + rgrp*3;
                op[0]=hv[0][ss]; op[1]=hv[1][ss]; op[2]=hv[2][ss];
            }
        }
        CL_WAIT();                         // acquire peers' h(t)
    }
}

// ---- layer1 bwd @ t=31 only (h0=c0=0) ----
__global__ void bwd1_last(const float* __restrict__ gxb, float* __restrict__ h2)
{
    int n = blockIdx.x, j = threadIdx.x;
    const float* g = gxb + (size_t)n*G;
    float iv = sigm(g[j]);
    float gv = tanhf(g[2*H+j]);
    float ov = sigm(g[3*H+j]);
    float cc = iv*gv;
    h2[(size_t)n*384 + 192 + j] = ov*tanhf(cc);
}

// ---- dynamic network ----
__global__ void dyn_scalars(const float* __restrict__ x, const float* __restrict__ theta,
                            int* __restrict__ pid, int* __restrict__ off)
{
    int n = blockIdx.x*blockDim.x + threadIdx.x;
    if (n >= NS) return;
    float th  = theta[n];
    float x30 = x[((size_t)n*T + 30)*NF];
    float x31 = x[((size_t)n*T + 31)*NF];
    int p0 = (x30 > th) ? 1 : ((x30 < -th) ? -1 : 0);
    int p1 = (x31 > th) ? 1 : ((x31 < -th) ? -1 : 0);
    pid[n] = (p0+1)*3 + (p1+1);
    off[n] = (p1+1)*3;
}

__global__ __launch_bounds__(256,1)
void dyn_beta(const float* __restrict__ PP, const int* __restrict__ pid,
              const int* __restrict__ off, float* __restrict__ BetaT,
              float* __restrict__ t3)
{
    __shared__ float s_raw[1024];
    __shared__ float s_adj[1024*3];
    __shared__ float s_red[256];
    const int y = blockIdx.x, tid = threadIdx.x;
    const int offy = off[y];
    for (int x=tid; x<NS; x+=256){
        size_t base = ((size_t)x*NS + y)*81 + (size_t)pid[x]*9 + offy;
        float a0=PP[base], a1=PP[base+1], a2=PP[base+2];
        s_adj[x*3+0]=a0; s_adj[x*3+1]=a1; s_adj[x*3+2]=a2;
        float nr = sqrtf(a0*a0+a1*a1+a2*a2);
        s_raw[x] = (nr > 0.38f) ? nr : 0.f;
    }
    __syncthreads();
    float lm = -1e30f;
    for (int x=tid; x<NS; x+=256) lm = fmaxf(lm, s_raw[x]);
    s_red[tid]=lm; __syncthreads();
    for (int o=128;o>0;o>>=1){ if(tid<o) s_red[tid]=fmaxf(s_red[tid],s_red[tid+o]); __syncthreads(); }
    const float mx = s_red[0];
    __syncthreads();
    float ls = 0.f;
    for (int x=tid; x<NS; x+=256){ float e=expf(s_raw[x]-mx); s_raw[x]=e; ls+=e; }
    s_red[tid]=ls; __syncthreads();
    for (int o=128;o>0;o>>=1){ if(tid<o) s_red[tid]+=s_red[tid+o]; __syncthreads(); }
    const float inv = 1.f/s_red[0];
    __syncthreads();
    float t0=0.f,t1=0.f,t2=0.f;
    for (int x=tid; x<NS; x+=256){
        float b = s_raw[x]*inv;
        BetaT[(size_t)y*NS + x] = b;
        t0 += b*s_adj[x*3+0]; t1 += b*s_adj[x*3+1]; t2 += b*s_adj[x*3+2];
    }
    s_red[tid]=t0; __syncthreads();
    for (int o=128;o>0;o>>=1){ if(tid<o) s_red[tid]+=s_red[tid+o]; __syncthreads(); }
    if(tid==0) t3[y*3+0]=s_red[0];
    __syncthreads();
    s_red[tid]=t1; __syncthreads();
    for (int o=128;o>0;o>>=1){ if(tid<o) s_red[tid]+=s_red[tid+o]; __syncthreads(); }
    if(tid==0) t3[y*3+1]=s_red[0];
    __syncthreads();
    s_red[tid]=t2; __syncthreads();
    for (int o=128;o>0;o>>=1){ if(tid<o) s_red[tid]+=s_red[tid+o]; __syncthreads(); }
    if(tid==0) t3[y*3+2]=s_red[0];
}

__global__ void agg_extra(const float* __restrict__ t3, const float* __restrict__ Wa,
                          const float* __restrict__ b, float* __restrict__ E)
{
    int y = blockIdx.x, u = threadIdx.x;
    float v = b[u] + t3[y*3+0]*Wa[u] + t3[y*3+1]*Wa[128+u] + t3[y*3+2]*Wa[256+u];
    E[(size_t)y*128 + u] = v;
}

// ---- final projection + tanh: warp per output ----
__global__ void out_kernel(const float* __restrict__ nfeat, const float* __restrict__ n1,
                           const float* __restrict__ n2, const float* __restrict__ W,
                           const float* __restrict__ b, float* __restrict__ out)
{
    int warp = (blockIdx.x*blockDim.x + threadIdx.x)>>5;
    int lane = threadIdx.x & 31;
    if (warp >= NS*2) return;
    int n = warp>>1, o = warp&1;
    float s = 0.f;
    for (int k=lane;k<384;k+=32) s += nfeat[(size_t)n*384+k]*W[k*2+o];
    for (int k=lane;k<128;k+=32) s += n1[(size_t)n*128+k]*W[(384+k)*2+o];
    for (int k=lane;k<128;k+=32) s += n2[(size_t)n*128+k]*W[(512+k)*2+o];
    #pragma unroll
    for (int m=16;m>0;m>>=1) s += __shfl_xor_sync(0xffffffffu, s, m);
    if (lane==0) out[warp] = tanhf(s + b[o]);
}

extern "C" void kernel_launch(void* const* d_in, const int* in_sizes, int n_in,
                              void* d_out, int out_size)
{
    const float* x     = (const float*)d_in[0];
    const float* theta = (const float*)d_in[1];
    const float* PP    = (const float*)d_in[2];
    const float* Wih0  = (const float*)d_in[3];
    const float* Whh0  = (const float*)d_in[4];
    const float* bih0  = (const float*)d_in[5];
    const float* bhh0  = (const float*)d_in[6];
    const float* Wih1  = (const float*)d_in[7];
    const float* Whh1  = (const float*)d_in[8];
    const float* bih1  = (const float*)d_in[9];
    const float* bhh1  = (const float*)d_in[10];
    const float* Wagg1 = (const float*)d_in[11];
    const float* bagg1 = (const float*)d_in[12];
    const float* Wagg2 = (const float*)d_in[13];
    const float* bagg2 = (const float*)d_in[14];
    const float* Wout  = (const float*)d_in[15];
    const float* bout  = (const float*)d_in[16];
    float* out = (float*)d_out;

    float *p_gx0, *p_gx1, *p_gx1b, *p_h1, *p_h2, *p_BetaT, *p_t3, *p_M, *p_E, *p_n1, *p_n2;
    int *p_pid, *p_off;
    cudaGetSymbolAddress((void**)&p_gx0,  g_gx0);
    cudaGetSymbolAddress((void**)&p_gx1,  g_gx1);
    cudaGetSymbolAddress((void**)&p_gx1b, g_gx1b);
    cudaGetSymbolAddress((void**)&p_h1,   g_h1);
    cudaGetSymbolAddress((void**)&p_h2,   g_h2);
    cudaGetSymbolAddress((void**)&p_BetaT,g_BetaT);
    cudaGetSymbolAddress((void**)&p_t3,   g_t3);
    cudaGetSymbolAddress((void**)&p_pid,  g_pid);
    cudaGetSymbolAddress((void**)&p_off,  g_off);
    cudaGetSymbolAddress((void**)&p_M,    g_M);
    cudaGetSymbolAddress((void**)&p_E,    g_E);
    cudaGetSymbolAddress((void**)&p_n1,   g_n1);
    cudaGetSymbolAddress((void**)&p_n2,   g_n2);

    const int SM64 = (192*196 + 64*202)*4;   // 202240 B
    const int SM32 = (192*196 + 32*202)*4;   // 176384 B
    cudaFuncSetAttribute(lstm_cluster<64>, cudaFuncAttributeMaxDynamicSharedMemorySize, SM64);
    cudaFuncSetAttribute(lstm_cluster<32>, cudaFuncAttributeMaxDynamicSharedMemorySize, SM32);

    // dynamic network
    dyn_scalars<<<4, 256>>>(x, theta, p_pid, p_off);
    dyn_beta<<<NS, 256>>>(PP, p_pid, p_off, p_BetaT, p_t3);

    // layer0 gx (both dirs)
    for (int d=0; d<2; d++){
        gemm_nt128<<<dim3(256,6), 256>>>(x, NF, Wih0 + (size_t)d*G*NF, NF,
                                         p_gx0 + (size_t)d*NS*T*G, G, NF,
                                         bih0 + d*G, bhh0 + d*G);
    }
    // layer0 recurrence: fwd + bwd in one cluster launch (128 CTAs, 1 wave)
    lstm_cluster<64><<<dim3(64,2), 256, SM64>>>(p_gx0, Whh0, p_h1, 0);

    // layer1 fwd gx
    gemm_nt128<<<dim3(256,6), 256>>>(p_h1, 384, Wih1, 384, p_gx1, G, 384,
                                     bih1, bhh1);
    // layer1 bwd gx at t=31 only
    gemm_nt128<<<dim3(8,6), 256>>>(p_h1 + 31*384, T*384, Wih1 + (size_t)G*384, 384,
                                   p_gx1b, G, 384, bih1 + G, bhh1 + G);

    // layer1 recurrence fwd (32 stocks/cluster -> 128 CTAs); bwd single step
    lstm_cluster<32><<<dim3(128,1), 256, SM32>>>(p_gx1, Whh1, p_h2, 2);
    bwd1_last<<<NS, H>>>(p_gx1b, p_h2);

    // agg layer 1
    gemm_nn64<<<dim3(16,2), 256>>>(p_h2, 384, Wagg1, 128, p_M, 128, 384, (const float*)0);
    agg_extra<<<NS, 128>>>(p_t3, Wagg1 + (size_t)384*128, bagg1, p_E);
    gemm_nn64<<<dim3(16,2), 256>>>(p_BetaT, NS, p_M, 128, p_n1, 128, NS, p_E);

    // agg layer 2
    gemm_nn64<<<dim3(16,2), 256>>>(p_n1, 128, Wagg2, 128, p_M, 128, 128, (const float*)0);
    agg_extra<<<NS, 128>>>(p_t3, Wagg2 + (size_t)128*128, bagg2, p_E);
    gemm_nn64<<<dim3(16,2), 256>>>(p_BetaT, NS, p_M, 128, p_n2, 128, NS, p_E);

    // output
    out_kernel<<<256, 256>>>(p_h2, p_n1, p_n2, Wout, bout, out);
}

// round 5
// speedup vs baseline: 1.9088x; 1.0574x over previous
#include <cuda_runtime.h>
#include <math.h>
#include <stdint.h>

#define NS 1024
#define T  32
#define NF 16
#define H  192
#define G  768

typedef unsigned long long u64;

static __device__ float g_gx0[(size_t)2*NS*T*G];
static __device__ float g_gx1[(size_t)NS*T*G];
static __device__ float g_gx1b[(size_t)NS*G];
static __device__ float g_h1[(size_t)NS*T*384];
static __device__ float g_h2[(size_t)NS*384];
static __device__ float g_BetaT[(size_t)NS*NS];
static __device__ float g_t3[NS*3];
static __device__ int   g_pid[NS];
static __device__ int   g_off[NS];
static __device__ float g_M[NS*128];
static __device__ float g_E[NS*128];
static __device__ float g_n1[NS*128];
static __device__ float g_n2[NS*128];

__device__ __forceinline__ float sigm(float x){ return 1.f/(1.f+expf(-x)); }
__device__ __forceinline__ u64 pk(float x, float y){ u64 r; asm("mov.b64 %0,{%1,%2};":"=l"(r):"f"(x),"f"(y)); return r; }
__device__ __forceinline__ void fma2(u64& d, u64 a, u64 b){ asm("fma.rn.f32x2 %0,%1,%2,%0;":"+l"(d):"l"(a),"l"(b)); }
__device__ __forceinline__ void unpk(u64 v, float& x, float& y){ asm("mov.b64 {%0,%1},%2;":"=f"(x),"=f"(y):"l"(v)); }
__device__ __forceinline__ float lohi(u64 v){ float x,y; unpk(v,x,y); return x+y; }
__device__ __forceinline__ uint32_t smem_u32(const void* p){
    uint32_t a; asm("{ .reg .u64 t; cvta.to.shared.u64 t, %1; cvt.u32.u64 %0, t; }":"=r"(a):"l"(p)); return a;
}
#define CL_ARRIVE() asm volatile("barrier.cluster.arrive.aligned;" ::: "memory")
#define CL_WAIT()   asm volatile("barrier.cluster.wait.aligned;"   ::: "memory")

// ---- C[m][n] = sum_k A[m][k]*B[n][k] + bias0[n] + bias1[n]
// 128x128 tile, BK=16, 256 threads, 8x8 microtile.
// f32x2 paired over m (rows 2*i2, 2*i2+1): A operands loaded directly as u64
// pairs from smem (no packing movs); b duplicated (8 movs/k). Scalar-order
// accumulation per output -> numerics identical to plain FFMA.
__global__ __launch_bounds__(256,2)
void gemm_nt128(const float* __restrict__ A, int lda,
                const float* __restrict__ B, int ldb,
                float* __restrict__ C, int ldc, int K,
                const float* __restrict__ bias0, const float* __restrict__ bias1)
{
    __shared__ __align__(16) float As[16][136];
    __shared__ __align__(16) float Bs[16][136];
    const int m0 = blockIdx.x*128, n0 = blockIdx.y*128;
    const int tid = threadIdx.x;
    const int ty = tid>>4, tx = tid&15;
    const int row = tid>>1, kq = (tid&1)*8;
    u64 acc[4][8];   // [i2][j], lanes = rows (2*i2, 2*i2+1)
    #pragma unroll
    for (int i=0;i<4;i++)
        #pragma unroll
        for (int j=0;j<8;j++) acc[i][j]=0ull;

    for (int k0=0;k0<K;k0+=16){
        float4 a0 = *(const float4*)(A + (size_t)(m0+row)*lda + k0 + kq);
        float4 a1 = *(const float4*)(A + (size_t)(m0+row)*lda + k0 + kq + 4);
        float4 b0 = *(const float4*)(B + (size_t)(n0+row)*ldb + k0 + kq);
        float4 b1 = *(const float4*)(B + (size_t)(n0+row)*ldb + k0 + kq + 4);
        __syncthreads();
        As[kq+0][row]=a0.x; As[kq+1][row]=a0.y; As[kq+2][row]=a0.z; As[kq+3][row]=a0.w;
        As[kq+4][row]=a1.x; As[kq+5][row]=a1.y; As[kq+6][row]=a1.z; As[kq+7][row]=a1.w;
        Bs[kq+0][row]=b0.x; Bs[kq+1][row]=b0.y; Bs[kq+2][row]=b0.z; Bs[kq+3][row]=b0.w;
        Bs[kq+4][row]=b1.x; Bs[kq+5][row]=b1.y; Bs[kq+6][row]=b1.z; Bs[kq+7][row]=b1.w;
        __syncthreads();
        #pragma unroll
        for (int k=0;k<16;k++){
            ulonglong2 av0 = *(const ulonglong2*)&As[k][ty*8];    // rows 0-1, 2-3
            ulonglong2 av1 = *(const ulonglong2*)&As[k][ty*8+4];  // rows 4-5, 6-7
            float4 bA = *(const float4*)&Bs[k][tx*8];
            float4 bB = *(const float4*)&Bs[k][tx*8+4];
            u64 bb[8];
            bb[0]=pk(bA.x,bA.x); bb[1]=pk(bA.y,bA.y); bb[2]=pk(bA.z,bA.z); bb[3]=pk(bA.w,bA.w);
            bb[4]=pk(bB.x,bB.x); bb[5]=pk(bB.y,bB.y); bb[6]=pk(bB.z,bB.z); bb[7]=pk(bB.w,bB.w);
            u64 aa[4] = { av0.x, av0.y, av1.x, av1.y };
            #pragma unroll
            for (int i2=0;i2<4;i2++)
                #pragma unroll
                for (int j=0;j<8;j++) fma2(acc[i2][j], aa[i2], bb[j]);
        }
    }
    float bv[8];
    #pragma unroll
    for (int j=0;j<8;j++){
        int n = n0+tx*8+j;
        float v = 0.f;
        if (bias0) v += bias0[n];
        if (bias1) v += bias1[n];
        bv[j]=v;
    }
    #pragma unroll
    for (int i2=0;i2<4;i2++){
        float r0[8], r1[8];
        #pragma unroll
        for (int j=0;j<8;j++){ unpk(acc[i2][j], r0[j], r1[j]); r0[j]+=bv[j]; r1[j]+=bv[j]; }
        float* c0 = C + (size_t)(m0+ty*8+2*i2)*ldc + n0 + tx*8;
        float* c1 = C + (size_t)(m0+ty*8+2*i2+1)*ldc + n0 + tx*8;
        *(float4*)c0     = make_float4(r0[0],r0[1],r0[2],r0[3]);
        *(float4*)(c0+4) = make_float4(r0[4],r0[5],r0[6],r0[7]);
        *(float4*)c1     = make_float4(r1[0],r1[1],r1[2],r1[3]);
        *(float4*)(c1+4) = make_float4(r1[4],r1[5],r1[6],r1[7]);
    }
}

// ---- C[m][n] = sum_k A[m][k]*B[k][n] (+addC), 64x64 tile, 4x4 micro.
__global__ __launch_bounds__(256,1)
void gemm_nn64(const float* __restrict__ A, int lda,
               const float* __restrict__ B, int ldb,
               float* __restrict__ C, int ldc, int K,
               const float* __restrict__ addC)
{
    __shared__ __align__(16) float As[16][68];
    __shared__ __align__(16) float Bs[16][68];
    const int m0 = blockIdx.x*64, n0 = blockIdx.y*64;
    const int tid = threadIdx.x;
    const int ty = tid>>4, tx = tid&15;
    const int arow = tid>>2, akq = (tid&3)*4;
    const int bk = tid>>4, bnq = (tid&15)*4;
    float acc[4][4];
    #pragma unroll
    for (int i=0;i<4;i++)
        #pragma unroll
        for (int j=0;j<4;j++) acc[i][j]=0.f;

    for (int k0=0;k0<K;k0+=16){
        float4 av = *(const float4*)(A + (size_t)(m0+arow)*lda + k0 + akq);
        float4 bv = *(const float4*)(B + (size_t)(k0+bk)*ldb + n0 + bnq);
        __syncthreads();
        As[akq+0][arow]=av.x; As[akq+1][arow]=av.y; As[akq+2][arow]=av.z; As[akq+3][arow]=av.w;
        *(float4*)&Bs[bk][bnq] = bv;
        __syncthreads();
        #pragma unroll
        for (int k=0;k<16;k++){
            float a[4],b[4];
            #pragma unroll
            for (int i=0;i<4;i++){ a[i]=As[k][ty*4+i]; b[i]=Bs[k][tx*4+i]; }
            #pragma unroll
            for (int i=0;i<4;i++)
                #pragma unroll
                for (int j=0;j<4;j++) acc[i][j]+=a[i]*b[j];
        }
    }
    #pragma unroll
    for (int i=0;i<4;i++){
        int m = m0+ty*4+i;
        float* cp = C + (size_t)m*ldc + n0 + tx*4;
        const float* ap = addC ? addC + (size_t)m*ldc + n0 + tx*4 : (const float*)0;
        #pragma unroll
        for (int j=0;j<4;j++){
            float v = acc[i][j];
            if (ap) v += ap[j];
            cp[j] = v;
        }
    }
}

// ---- cluster LSTM recurrence: Whh resident in smem across all 32 steps.
// Cluster of 4 CTAs; rank r owns gate-unit slice [r*48, r*48+48) of all 4
// gates (192 rows x 192 k, staged once). 512 threads (4 warps/SMSP):
// sgrp = tid&31 (stock), rgrp = tid>>5 (3 units each). gx prefetched into
// registers at step top. After pointwise, h slice pushed to 3 peers via
// DSMEM + local STS. mode = mode0 + blockIdx.y.
template<int SPC>
__global__ __launch_bounds__(512,1) __cluster_dims__(4,1,1)
void lstm_cluster(const float* __restrict__ gx_all, const float* __restrict__ Whh_all,
                  float* __restrict__ outp, int mode0)
{
    constexpr int SPT = SPC/32;        // stocks per thread
    constexpr int HSP = 202;           // Hs row stride (floats)
    constexpr int BSP = 196;           // Bsh row stride
    extern __shared__ float sm[];
    float* Bsh = sm;                   // [192][BSP]
    float* Hs  = sm + 192*BSP;         // [SPC][HSP]

    const int dir  = blockIdx.y;
    const int mode = mode0 + dir;
    const float* gx  = gx_all  + (size_t)dir*NS*T*G;
    const float* Whh = Whh_all + (size_t)dir*G*H;

    const int tid  = threadIdx.x;
    const int sgrp = tid & 31;         // stocks sgrp + 32*ss
    const int rgrp = tid >> 5;         // 0..15 -> units rgrp*3 + {0,1,2}
    uint32_t rank; asm("mov.u32 %0, %%cluster_ctarank;" : "=r"(rank));
    const int cid   = blockIdx.x >> 2;
    const int sbase = cid * SPC;
    const int jsl   = (int)rank * 48;
    const uint32_t hs_base = smem_u32(Hs);

    // stage Whh slice once: local row lr = q*48+u <- global row q*192+jsl+u
    for (int i = tid; i < 192*48; i += 512){
        int lr = i / 48, c4 = i % 48;
        int q = lr / 48, u = lr % 48;
        float4 v = *(const float4*)(Whh + (size_t)(q*192 + jsl + u)*H + c4*4);
        *(float4*)(Bsh + lr*BSP + c4*4) = v;
    }
    for (int i = tid; i < SPC*HSP; i += 512) Hs[i] = 0.f;
    CL_ARRIVE(); CL_WAIT();

    float c[3][SPT];
    #pragma unroll
    for (int a=0;a<3;a++)
        #pragma unroll
        for (int b=0;b<SPT;b++) c[a][b]=0.f;

    for (int step=0; step<T; ++step){
        const int tt = (mode==1) ? (T-1-step) : step;

        // prefetch gx for this step (hidden behind the matvec below)
        float gxr[3][4][SPT];
        #pragma unroll
        for (int ss=0;ss<SPT;ss++){
            const float* gp = gx + ((size_t)(sbase + sgrp + 32*ss)*T + tt)*G;
            #pragma unroll
            for (int uu=0;uu<3;uu++)
                #pragma unroll
                for (int q=0;q<4;q++)
                    gxr[uu][q][ss] = gp[q*192 + jsl + rgrp*3 + uu];
        }

        u64 acc[3][4][SPT];
        #pragma unroll
        for (int uu=0;uu<3;uu++)
            #pragma unroll
            for (int q=0;q<4;q++)
                #pragma unroll
                for (int ss=0;ss<SPT;ss++) acc[uu][q][ss]=0ull;

        #pragma unroll 1
        for (int k=0;k<192;k+=4){
            u64 h0[SPT], h1[SPT];
            #pragma unroll
            for (int ss=0;ss<SPT;ss++){
                const float* hp = Hs + (sgrp + 32*ss)*HSP + k;
                h0[ss] = *(const u64*)hp;
                h1[ss] = *(const u64*)(hp+2);
            }
            #pragma unroll
            for (int uu=0;uu<3;uu++)
                #pragma unroll
                for (int q=0;q<4;q++){
                    ulonglong2 bv = *(const ulonglong2*)(Bsh + (q*48 + rgrp*3 + uu)*BSP + k);
                    #pragma unroll
                    for (int ss=0;ss<SPT;ss++){
                        fma2(acc[uu][q][ss], h0[ss], bv.x);
                        fma2(acc[uu][q][ss], h1[ss], bv.y);
                    }
                }
        }
        float pre[3][4][SPT];
        #pragma unroll
        for (int uu=0;uu<3;uu++)
            #pragma unroll
            for (int q=0;q<4;q++)
                #pragma unroll
                for (int ss=0;ss<SPT;ss++) pre[uu][q][ss] = lohi(acc[uu][q][ss]) + gxr[uu][q][ss];

        CL_ARRIVE();                       // my reads of Hs(t-1) done
        CL_WAIT();                         // everyone's reads done -> safe to write

        float hv[3][SPT];
        #pragma unroll
        for (int uu=0;uu<3;uu++)
            #pragma unroll
            for (int ss=0;ss<SPT;ss++){
                float iv = sigm(pre[uu][0][ss]);
                float fv = sigm(pre[uu][1][ss]);
                float gv = tanhf(pre[uu][2][ss]);
                float ov = sigm(pre[uu][3][ss]);
                float cc = fv*c[uu][ss] + iv*gv;
                c[uu][ss] = cc;
                hv[uu][ss] = ov*tanhf(cc);
            }
        // push h slice: local STS + 3 remote DSMEM stores
        #pragma unroll
        for (int ss=0;ss<SPT;ss++){
            int sl = sgrp + 32*ss;
            #pragma unroll
            for (int uu=0;uu<3;uu++){
                uint32_t la = hs_base + (uint32_t)(sl*HSP + jsl + rgrp*3 + uu)*4u;
                float v = hv[uu][ss];
                Hs[sl*HSP + jsl + rgrp*3 + uu] = v;
                #pragma unroll
                for (int r=0;r<4;r++){
                    if (r == (int)rank) continue;
                    uint32_t da; asm("mapa.shared::cluster.u32 %0,%1,%2;":"=r"(da):"r"(la),"r"(r));
                    asm volatile("st.shared::cluster.f32 [%0],%1;"::"r"(da),"f"(v));
                }
            }
        }
        CL_ARRIVE();                       // release h(t) writes
        // global output stores hidden before the wait
        if (mode==0 || mode==1){
            #pragma unroll
            for (int ss=0;ss<SPT;ss++){
                int s = sbase + sgrp + 32*ss;
                float* op = outp + ((size_t)s*T + tt)*384 + (mode==1?192:0) + jsl + rgrp*3;
                op[0]=hv[0][ss]; op[1]=hv[1][ss]; op[2]=hv[2][ss];
            }
        } else if (step==T-1){
            #pragma unroll
            for (int ss=0;ss<SPT;ss++){
                int s = sbase + sgrp + 32*ss;
                float* op = outp + (size_t)s*384 + jsl + rgrp*3;
                op[0]=hv[0][ss]; op[1]=hv[1][ss]; op[2]=hv[2][ss];
            }
        }
        CL_WAIT();                         // acquire peers' h(t)
    }
}

// ---- layer1 bwd @ t=31 only (h0=c0=0) ----
__global__ void bwd1_last(const float* __restrict__ gxb, float* __restrict__ h2)
{
    int n = blockIdx.x, j = threadIdx.x;
    const float* g = gxb + (size_t)n*G;
    float iv = sigm(g[j]);
    float gv = tanhf(g[2*H+j]);
    float ov = sigm(g[3*H+j]);
    float cc = iv*gv;
    h2[(size_t)n*384 + 192 + j] = ov*tanhf(cc);
}

// ---- dynamic network ----
__global__ void dyn_scalars(const float* __restrict__ x, const float* __restrict__ theta,
                            int* __restrict__ pid, int* __restrict__ off)
{
    int n = blockIdx.x*blockDim.x + threadIdx.x;
    if (n >= NS) return;
    float th  = theta[n];
    float x30 = x[((size_t)n*T + 30)*NF];
    float x31 = x[((size_t)n*T + 31)*NF];
    int p0 = (x30 > th) ? 1 : ((x30 < -th) ? -1 : 0);
    int p1 = (x31 > th) ? 1 : ((x31 < -th) ? -1 : 0);
    pid[n] = (p0+1)*3 + (p1+1);
    off[n] = (p1+1)*3;
}

__global__ __launch_bounds__(256,1)
void dyn_beta(const float* __restrict__ PP, const int* __restrict__ pid,
              const int* __restrict__ off, float* __restrict__ BetaT,
              float* __restrict__ t3)
{
    __shared__ float s_raw[1024];
    __shared__ float s_adj[1024*3];
    __shared__ float s_red[256];
    const int y = blockIdx.x, tid = threadIdx.x;
    const int offy = off[y];
    for (int x=tid; x<NS; x+=256){
        size_t base = ((size_t)x*NS + y)*81 + (size_t)pid[x]*9 + offy;
        float a0=PP[base], a1=PP[base+1], a2=PP[base+2];
        s_adj[x*3+0]=a0; s_adj[x*3+1]=a1; s_adj[x*3+2]=a2;
        float nr = sqrtf(a0*a0+a1*a1+a2*a2);
        s_raw[x] = (nr > 0.38f) ? nr : 0.f;
    }
    __syncthreads();
    float lm = -1e30f;
    for (int x=tid; x<NS; x+=256) lm = fmaxf(lm, s_raw[x]);
    s_red[tid]=lm; __syncthreads();
    for (int o=128;o>0;o>>=1){ if(tid<o) s_red[tid]=fmaxf(s_red[tid],s_red[tid+o]); __syncthreads(); }
    const float mx = s_red[0];
    __syncthreads();
    float ls = 0.f;
    for (int x=tid; x<NS; x+=256){ float e=expf(s_raw[x]-mx); s_raw[x]=e; ls+=e; }
    s_red[tid]=ls; __syncthreads();
    for (int o=128;o>0;o>>=1){ if(tid<o) s_red[tid]+=s_red[tid+o]; __syncthreads(); }
    const float inv = 1.f/s_red[0];
    __syncthreads();
    float t0=0.f,t1=0.f,t2=0.f;
    for (int x=tid; x<NS; x+=256){
        float b = s_raw[x]*inv;
        BetaT[(size_t)y*NS + x] = b;
        t0 += b*s_adj[x*3+0]; t1 += b*s_adj[x*3+1]; t2 += b*s_adj[x*3+2];
    }
    s_red[tid]=t0; __syncthreads();
    for (int o=128;o>0;o>>=1){ if(tid<o) s_red[tid]+=s_red[tid+o]; __syncthreads(); }
    if(tid==0) t3[y*3+0]=s_red[0];
    __syncthreads();
    s_red[tid]=t1; __syncthreads();
    for (int o=128;o>0;o>>=1){ if(tid<o) s_red[tid]+=s_red[tid+o]; __syncthreads(); }
    if(tid==0) t3[y*3+1]=s_red[0];
    __syncthreads();
    s_red[tid]=t2; __syncthreads();
    for (int o=128;o>0;o>>=1){ if(tid<o) s_red[tid]+=s_red[tid+o]; __syncthreads(); }
    if(tid==0) t3[y*3+2]=s_red[0];
}

__global__ void agg_extra(const float* __restrict__ t3, const float* __restrict__ Wa,
                          const float* __restrict__ b, float* __restrict__ E)
{
    int y = blockIdx.x, u = threadIdx.x;
    float v = b[u] + t3[y*3+0]*Wa[u] + t3[y*3+1]*Wa[128+u] + t3[y*3+2]*Wa[256+u];
    E[(size_t)y*128 + u] = v;
}

// ---- final projection + tanh: warp per output ----
__global__ void out_kernel(const float* __restrict__ nfeat, const float* __restrict__ n1,
                           const float* __restrict__ n2, const float* __restrict__ W,
                           const float* __restrict__ b, float* __restrict__ out)
{
    int warp = (blockIdx.x*blockDim.x + threadIdx.x)>>5;
    int lane = threadIdx.x & 31;
    if (warp >= NS*2) return;
    int n = warp>>1, o = warp&1;
    float s = 0.f;
    for (int k=lane;k<384;k+=32) s += nfeat[(size_t)n*384+k]*W[k*2+o];
    for (int k=lane;k<128;k+=32) s += n1[(size_t)n*128+k]*W[(384+k)*2+o];
    for (int k=lane;k<128;k+=32) s += n2[(size_t)n*128+k]*W[(512+k)*2+o];
    #pragma unroll
    for (int m=16;m>0;m>>=1) s += __shfl_xor_sync(0xffffffffu, s, m);
    if (lane==0) out[warp] = tanhf(s + b[o]);
}

extern "C" void kernel_launch(void* const* d_in, const int* in_sizes, int n_in,
                              void* d_out, int out_size)
{
    const float* x     = (const float*)d_in[0];
    const float* theta = (const float*)d_in[1];
    const float* PP    = (const float*)d_in[2];
    const float* Wih0  = (const float*)d_in[3];
    const float* Whh0  = (const float*)d_in[4];
    const float* bih0  = (const float*)d_in[5];
    const float* bhh0  = (const float*)d_in[6];
    const float* Wih1  = (const float*)d_in[7];
    const float* Whh1  = (const float*)d_in[8];
    const float* bih1  = (const float*)d_in[9];
    const float* bhh1  = (const float*)d_in[10];
    const float* Wagg1 = (const float*)d_in[11];
    const float* bagg1 = (const float*)d_in[12];
    const float* Wagg2 = (const float*)d_in[13];
    const float* bagg2 = (const float*)d_in[14];
    const float* Wout  = (const float*)d_in[15];
    const float* bout  = (const float*)d_in[16];
    float* out = (float*)d_out;

    float *p_gx0, *p_gx1, *p_gx1b, *p_h1, *p_h2, *p_BetaT, *p_t3, *p_M, *p_E, *p_n1, *p_n2;
    int *p_pid, *p_off;
    cudaGetSymbolAddress((void**)&p_gx0,  g_gx0);
    cudaGetSymbolAddress((void**)&p_gx1,  g_gx1);
    cudaGetSymbolAddress((void**)&p_gx1b, g_gx1b);
    cudaGetSymbolAddress((void**)&p_h1,   g_h1);
    cudaGetSymbolAddress((void**)&p_h2,   g_h2);
    cudaGetSymbolAddress((void**)&p_BetaT,g_BetaT);
    cudaGetSymbolAddress((void**)&p_t3,   g_t3);
    cudaGetSymbolAddress((void**)&p_pid,  g_pid);
    cudaGetSymbolAddress((void**)&p_off,  g_off);
    cudaGetSymbolAddress((void**)&p_M,    g_M);
    cudaGetSymbolAddress((void**)&p_E,    g_E);
    cudaGetSymbolAddress((void**)&p_n1,   g_n1);
    cudaGetSymbolAddress((void**)&p_n2,   g_n2);

    const int SM64 = (192*196 + 64*202)*4;   // 202240 B
    const int SM32 = (192*196 + 32*202)*4;   // 176384 B
    cudaFuncSetAttribute(lstm_cluster<64>, cudaFuncAttributeMaxDynamicSharedMemorySize, SM64);
    cudaFuncSetAttribute(lstm_cluster<32>, cudaFuncAttributeMaxDynamicSharedMemorySize, SM32);

    // #1-2: dynamic network
    dyn_scalars<<<4, 256>>>(x, theta, p_pid, p_off);
    dyn_beta<<<NS, 256>>>(PP, p_pid, p_off, p_BetaT, p_t3);

    // #3-4: layer0 gx (both dirs)
    for (int d=0; d<2; d++){
        gemm_nt128<<<dim3(256,6), 256>>>(x, NF, Wih0 + (size_t)d*G*NF, NF,
                                         p_gx0 + (size_t)d*NS*T*G, G, NF,
                                         bih0 + d*G, bhh0 + d*G);
    }
    // #5: E1 (independent; placed here so lstm lands on the profiled slot #6)
    agg_extra<<<NS, 128>>>(p_t3, Wagg1 + (size_t)384*128, bagg1, p_E);

    // #6: layer0 recurrence, fwd+bwd (128 CTAs, 1 wave) — profiled by ncu -s 5
    lstm_cluster<64><<<dim3(64,2), 512, SM64>>>(p_gx0, Whh0, p_h1, 0);

    // #7: layer1 fwd gx
    gemm_nt128<<<dim3(256,6), 256>>>(p_h1, 384, Wih1, 384, p_gx1, G, 384,
                                     bih1, bhh1);
    // #8: layer1 bwd gx at t=31 only
    gemm_nt128<<<dim3(8,6), 256>>>(p_h1 + 31*384, T*384, Wih1 + (size_t)G*384, 384,
                                   p_gx1b, G, 384, bih1 + G, bhh1 + G);

    // #9-10: layer1 recurrence fwd; bwd single step
    lstm_cluster<32><<<dim3(128,1), 512, SM32>>>(p_gx1, Whh1, p_h2, 2);
    bwd1_last<<<NS, H>>>(p_gx1b, p_h2);

    // #11-12: agg layer 1 (E1 already in p_E)
    gemm_nn64<<<dim3(16,2), 256>>>(p_h2, 384, Wagg1, 128, p_M, 128, 384, (const float*)0);
    gemm_nn64<<<dim3(16,2), 256>>>(p_BetaT, NS, p_M, 128, p_n1, 128, NS, p_E);

    // #13-15: agg layer 2
    gemm_nn64<<<dim3(16,2), 256>>>(p_n1, 128, Wagg2, 128, p_M, 128, 128, (const float*)0);
    agg_extra<<<NS, 128>>>(p_t3, Wagg2 + (size_t)128*128, bagg2, p_E);
    gemm_nn64<<<dim3(16,2), 256>>>(p_BetaT, NS, p_M, 128, p_n2, 128, NS, p_E);

    // #16: output
    out_kernel<<<256, 256>>>(p_h2, p_n1, p_n2, Wout, bout, out);
}

// round 6
// speedup vs baseline: 2.2008x; 1.1529x over previous
#include <cuda_runtime.h>
#include <math.h>
#include <stdint.h>

#define NS 1024
#define T  32
#define NF 16
#define H  192
#define G  768

typedef unsigned long long u64;

static __device__ float g_gx0[(size_t)2*NS*T*G];   // time-major: [dir][tt][G][NS]
static __device__ float g_gx1[(size_t)NS*T*G];     // time-major: [tt][G][NS]
static __device__ float g_gx1b[(size_t)NS*G];      // [s][G]
static __device__ float g_h1[(size_t)NS*T*384];    // [s][tt][384]
static __device__ float g_h2[(size_t)NS*384];
static __device__ float g_BetaT[(size_t)NS*NS];
static __device__ float g_t3[NS*3];
static __device__ int   g_pid[NS];
static __device__ int   g_off[NS];
static __device__ float g_M[NS*128];
static __device__ float g_E[NS*128];
static __device__ float g_n1[NS*128];
static __device__ float g_n2[NS*128];

__device__ __forceinline__ float sigm(float x){ return 1.f/(1.f+expf(-x)); }
__device__ __forceinline__ u64 pk(float x, float y){ u64 r; asm("mov.b64 %0,{%1,%2};":"=l"(r):"f"(x),"f"(y)); return r; }
__device__ __forceinline__ void fma2(u64& d, u64 a, u64 b){ asm("fma.rn.f32x2 %0,%1,%2,%0;":"+l"(d):"l"(a),"l"(b)); }
__device__ __forceinline__ void unpk(u64 v, float& x, float& y){ asm("mov.b64 {%0,%1},%2;":"=f"(x),"=f"(y):"l"(v)); }
__device__ __forceinline__ float lohi(u64 v){ float x,y; unpk(v,x,y); return x+y; }
__device__ __forceinline__ uint32_t smem_u32(const void* p){
    uint32_t a; asm("{ .reg .u64 t; cvta.to.shared.u64 t, %1; cvt.u32.u64 %0, t; }":"=r"(a):"l"(p)); return a;
}
#define CL_ARRIVE() asm volatile("barrier.cluster.arrive.aligned;" ::: "memory")
#define CL_WAIT()   asm volatile("barrier.cluster.wait.aligned;"   ::: "memory")

// ---- transposing gx GEMM: Ct[tt][n][s] = sum_k A[s][tt][k]*B[n][k] + biases
// Block: blockIdx.x = tt*8 + s-block(128), blockIdx.y = n-block(128).
// Microtile roles: rows (s-local) = tx*8+i, cols (n-local) = ty*8+j.
// Epilogue transposes through dynamic smem csh[128][132], stores coalesced
// 512B runs along s.
__global__ __launch_bounds__(256,2)
void gemm_nt128T(const float* __restrict__ A, int lda,
                 const float* __restrict__ B, int ldb,
                 float* __restrict__ Ct, int K,
                 const float* __restrict__ bias0, const float* __restrict__ bias1)
{
    extern __shared__ __align__(16) float csh[];   // [128][132]
    __shared__ __align__(16) float As[16][136];
    __shared__ __align__(16) float Bs[16][136];
    const int tt = blockIdx.x >> 3;
    const int s0 = (blockIdx.x & 7) * 128;
    const int n0 = blockIdx.y * 128;
    const int tid = threadIdx.x;
    const int ty = tid>>4, tx = tid&15;
    const int row = tid>>1, kq = (tid&1)*8;
    u64 acc[4][8];   // [i2][j]: rows (tx*8+2*i2, +1), cols ty*8+j
    #pragma unroll
    for (int i=0;i<4;i++)
        #pragma unroll
        for (int j=0;j<8;j++) acc[i][j]=0ull;

    for (int k0=0;k0<K;k0+=16){
        const float* ap = A + ((size_t)(s0+row)*T + tt)*lda + k0 + kq;
        float4 a0 = *(const float4*)ap;
        float4 a1 = *(const float4*)(ap+4);
        float4 b0 = *(const float4*)(B + (size_t)(n0+row)*ldb + k0 + kq);
        float4 b1 = *(const float4*)(B + (size_t)(n0+row)*ldb + k0 + kq + 4);
        __syncthreads();
        As[kq+0][row]=a0.x; As[kq+1][row]=a0.y; As[kq+2][row]=a0.z; As[kq+3][row]=a0.w;
        As[kq+4][row]=a1.x; As[kq+5][row]=a1.y; As[kq+6][row]=a1.z; As[kq+7][row]=a1.w;
        Bs[kq+0][row]=b0.x; Bs[kq+1][row]=b0.y; Bs[kq+2][row]=b0.z; Bs[kq+3][row]=b0.w;
        Bs[kq+4][row]=b1.x; Bs[kq+5][row]=b1.y; Bs[kq+6][row]=b1.z; Bs[kq+7][row]=b1.w;
        __syncthreads();
        #pragma unroll
        for (int k=0;k<16;k++){
            ulonglong2 av0 = *(const ulonglong2*)&As[k][tx*8];
            ulonglong2 av1 = *(const ulonglong2*)&As[k][tx*8+4];
            float4 bA = *(const float4*)&Bs[k][ty*8];
            float4 bB = *(const float4*)&Bs[k][ty*8+4];
            u64 bb[8];
            bb[0]=pk(bA.x,bA.x); bb[1]=pk(bA.y,bA.y); bb[2]=pk(bA.z,bA.z); bb[3]=pk(bA.w,bA.w);
            bb[4]=pk(bB.x,bB.x); bb[5]=pk(bB.y,bB.y); bb[6]=pk(bB.z,bB.z); bb[7]=pk(bB.w,bB.w);
            u64 aa[4] = { av0.x, av0.y, av1.x, av1.y };
            #pragma unroll
            for (int i2=0;i2<4;i2++)
                #pragma unroll
                for (int j=0;j<8;j++) fma2(acc[i2][j], aa[i2], bb[j]);
        }
    }
    float bv[8];
    #pragma unroll
    for (int j=0;j<8;j++){
        int n = n0+ty*8+j;
        bv[j] = bias0[n] + bias1[n];
    }
    __syncthreads();
    // stage transposed: csh[n_local][s_local]
    #pragma unroll
    for (int j=0;j<8;j++){
        float r[8];
        #pragma unroll
        for (int i2=0;i2<4;i2++){ unpk(acc[i2][j], r[2*i2], r[2*i2+1]); }
        #pragma unroll
        for (int v=0;v<8;v++) r[v] += bv[j];
        float* cp = csh + (size_t)(ty*8+j)*132 + tx*8;
        *(float4*)cp     = make_float4(r[0],r[1],r[2],r[3]);
        *(float4*)(cp+4) = make_float4(r[4],r[5],r[6],r[7]);
    }
    __syncthreads();
    // store: thread t -> j-row t>>1, s-half (t&1)*64
    {
        int jl = tid>>1, half = (tid&1)*64;
        const float* src = csh + (size_t)jl*132 + half;
        float* dst = Ct + ((size_t)tt*G + n0 + jl)*NS + s0 + half;
        #pragma unroll
        for (int v=0;v<16;v++)
            *(float4*)(dst + v*4) = *(const float4*)(src + v*4);
    }
}

// ---- plain NT gemm (used for gx1b): C[m][n] layout ----
__global__ __launch_bounds__(256,2)
void gemm_nt128(const float* __restrict__ A, int lda,
                const float* __restrict__ B, int ldb,
                float* __restrict__ C, int ldc, int K,
                const float* __restrict__ bias0, const float* __restrict__ bias1)
{
    __shared__ __align__(16) float As[16][136];
    __shared__ __align__(16) float Bs[16][136];
    const int m0 = blockIdx.x*128, n0 = blockIdx.y*128;
    const int tid = threadIdx.x;
    const int ty = tid>>4, tx = tid&15;
    const int row = tid>>1, kq = (tid&1)*8;
    u64 acc[4][8];
    #pragma unroll
    for (int i=0;i<4;i++)
        #pragma unroll
        for (int j=0;j<8;j++) acc[i][j]=0ull;

    for (int k0=0;k0<K;k0+=16){
        float4 a0 = *(const float4*)(A + (size_t)(m0+row)*lda + k0 + kq);
        float4 a1 = *(const float4*)(A + (size_t)(m0+row)*lda + k0 + kq + 4);
        float4 b0 = *(const float4*)(B + (size_t)(n0+row)*ldb + k0 + kq);
        float4 b1 = *(const float4*)(B + (size_t)(n0+row)*ldb + k0 + kq + 4);
        __syncthreads();
        As[kq+0][row]=a0.x; As[kq+1][row]=a0.y; As[kq+2][row]=a0.z; As[kq+3][row]=a0.w;
        As[kq+4][row]=a1.x; As[kq+5][row]=a1.y; As[kq+6][row]=a1.z; As[kq+7][row]=a1.w;
        Bs[kq+0][row]=b0.x; Bs[kq+1][row]=b0.y; Bs[kq+2][row]=b0.z; Bs[kq+3][row]=b0.w;
        Bs[kq+4][row]=b1.x; Bs[kq+5][row]=b1.y; Bs[kq+6][row]=b1.z; Bs[kq+7][row]=b1.w;
        __syncthreads();
        #pragma unroll
        for (int k=0;k<16;k++){
            ulonglong2 av0 = *(const ulonglong2*)&As[k][ty*8];
            ulonglong2 av1 = *(const ulonglong2*)&As[k][ty*8+4];
            float4 bA = *(const float4*)&Bs[k][tx*8];
            float4 bB = *(const float4*)&Bs[k][tx*8+4];
            u64 bb[8];
            bb[0]=pk(bA.x,bA.x); bb[1]=pk(bA.y,bA.y); bb[2]=pk(bA.z,bA.z); bb[3]=pk(bA.w,bA.w);
            bb[4]=pk(bB.x,bB.x); bb[5]=pk(bB.y,bB.y); bb[6]=pk(bB.z,bB.z); bb[7]=pk(bB.w,bB.w);
            u64 aa[4] = { av0.x, av0.y, av1.x, av1.y };
            #pragma unroll
            for (int i2=0;i2<4;i2++)
                #pragma unroll
                for (int j=0;j<8;j++) fma2(acc[i2][j], aa[i2], bb[j]);
        }
    }
    float bv[8];
    #pragma unroll
    for (int j=0;j<8;j++){
        int n = n0+tx*8+j;
        float v = 0.f;
        if (bias0) v += bias0[n];
        if (bias1) v += bias1[n];
        bv[j]=v;
    }
    #pragma unroll
    for (int i2=0;i2<4;i2++){
        float r0[8], r1[8];
        #pragma unroll
        for (int j=0;j<8;j++){ unpk(acc[i2][j], r0[j], r1[j]); r0[j]+=bv[j]; r1[j]+=bv[j]; }
        float* c0 = C + (size_t)(m0+ty*8+2*i2)*ldc + n0 + tx*8;
        float* c1 = C + (size_t)(m0+ty*8+2*i2+1)*ldc + n0 + tx*8;
        *(float4*)c0     = make_float4(r0[0],r0[1],r0[2],r0[3]);
        *(float4*)(c0+4) = make_float4(r0[4],r0[5],r0[6],r0[7]);
        *(float4*)c1     = make_float4(r1[0],r1[1],r1[2],r1[3]);
        *(float4*)(c1+4) = make_float4(r1[4],r1[5],r1[6],r1[7]);
    }
}

// ---- C[m][n] = sum_k A[m][k]*B[k][n] (+addC), 64x64 tile, 4x4 micro.
__global__ __launch_bounds__(256,1)
void gemm_nn64(const float* __restrict__ A, int lda,
               const float* __restrict__ B, int ldb,
               float* __restrict__ C, int ldc, int K,
               const float* __restrict__ addC)
{
    __shared__ __align__(16) float As[16][68];
    __shared__ __align__(16) float Bs[16][68];
    const int m0 = blockIdx.x*64, n0 = blockIdx.y*64;
    const int tid = threadIdx.x;
    const int ty = tid>>4, tx = tid&15;
    const int arow = tid>>2, akq = (tid&3)*4;
    const int bk = tid>>4, bnq = (tid&15)*4;
    float acc[4][4];
    #pragma unroll
    for (int i=0;i<4;i++)
        #pragma unroll
        for (int j=0;j<4;j++) acc[i][j]=0.f;

    for (int k0=0;k0<K;k0+=16){
        float4 av = *(const float4*)(A + (size_t)(m0+arow)*lda + k0 + akq);
        float4 bv = *(const float4*)(B + (size_t)(k0+bk)*ldb + n0 + bnq);
        __syncthreads();
        As[akq+0][arow]=av.x; As[akq+1][arow]=av.y; As[akq+2][arow]=av.z; As[akq+3][arow]=av.w;
        *(float4*)&Bs[bk][bnq] = bv;
        __syncthreads();
        #pragma unroll
        for (int k=0;k<16;k++){
            float a[4],b[4];
            #pragma unroll
            for (int i=0;i<4;i++){ a[i]=As[k][ty*4+i]; b[i]=Bs[k][tx*4+i]; }
            #pragma unroll
            for (int i=0;i<4;i++)
                #pragma unroll
                for (int j=0;j<4;j++) acc[i][j]+=a[i]*b[j];
        }
    }
    #pragma unroll
    for (int i=0;i<4;i++){
        int m = m0+ty*4+i;
        float* cp = C + (size_t)m*ldc + n0 + tx*4;
        const float* ap = addC ? addC + (size_t)m*ldc + n0 + tx*4 : (const float*)0;
        #pragma unroll
        for (int j=0;j<4;j++){
            float v = acc[i][j];
            if (ap) v += ap[j];
            cp[j] = v;
        }
    }
}

// ---- cluster LSTM recurrence (time-major gx): Whh resident in smem.
// gx layout: [tt][G][NS] (per dir) -> lane (stock) loads are coalesced.
template<int SPC>
__global__ __launch_bounds__(512,1) __cluster_dims__(4,1,1)
void lstm_cluster(const float* __restrict__ gx_all, const float* __restrict__ Whh_all,
                  float* __restrict__ outp, int mode0)
{
    constexpr int SPT = SPC/32;
    constexpr int HSP = 202;
    constexpr int BSP = 196;
    extern __shared__ float sm[];
    float* Bsh = sm;                   // [192][BSP]
    float* Hs  = sm + 192*BSP;         // [SPC][HSP]

    const int dir  = blockIdx.y;
    const int mode = mode0 + dir;
    const float* gx  = gx_all  + (size_t)dir*NS*T*G;
    const float* Whh = Whh_all + (size_t)dir*G*H;

    const int tid  = threadIdx.x;
    const int sgrp = tid & 31;
    const int rgrp = tid >> 5;
    uint32_t rank; asm("mov.u32 %0, %%cluster_ctarank;" : "=r"(rank));
    const int cid   = blockIdx.x >> 2;
    const int sbase = cid * SPC;
    const int jsl   = (int)rank * 48;
    const uint32_t hs_base = smem_u32(Hs);

    for (int i = tid; i < 192*48; i += 512){
        int lr = i / 48, c4 = i % 48;
        int q = lr / 48, u = lr % 48;
        float4 v = *(const float4*)(Whh + (size_t)(q*192 + jsl + u)*H + c4*4);
        *(float4*)(Bsh + lr*BSP + c4*4) = v;
    }
    for (int i = tid; i < SPC*HSP; i += 512) Hs[i] = 0.f;
    CL_ARRIVE(); CL_WAIT();

    float c[3][SPT];
    #pragma unroll
    for (int a=0;a<3;a++)
        #pragma unroll
        for (int b=0;b<SPT;b++) c[a][b]=0.f;

    for (int step=0; step<T; ++step){
        const int tt = (mode==1) ? (T-1-step) : step;

        // coalesced gx prefetch: lanes = stocks, contiguous in memory
        float gxr[3][4][SPT];
        #pragma unroll
        for (int uu=0;uu<3;uu++)
            #pragma unroll
            for (int q=0;q<4;q++)
                #pragma unroll
                for (int ss=0;ss<SPT;ss++)
                    gxr[uu][q][ss] = gx[((size_t)tt*G + q*192 + jsl + rgrp*3 + uu)*NS
                                        + sbase + sgrp + 32*ss];

        u64 acc[3][4][SPT];
        #pragma unroll
        for (int uu=0;uu<3;uu++)
            #pragma unroll
            for (int q=0;q<4;q++)
                #pragma unroll
                for (int ss=0;ss<SPT;ss++) acc[uu][q][ss]=0ull;

        #pragma unroll 1
        for (int k=0;k<192;k+=4){
            u64 h0[SPT], h1[SPT];
            #pragma unroll
            for (int ss=0;ss<SPT;ss++){
                const float* hp = Hs + (sgrp + 32*ss)*HSP + k;
                h0[ss] = *(const u64*)hp;
                h1[ss] = *(const u64*)(hp+2);
            }
            #pragma unroll
            for (int uu=0;uu<3;uu++)
                #pragma unroll
                for (int q=0;q<4;q++){
                    ulonglong2 bv = *(const ulonglong2*)(Bsh + (q*48 + rgrp*3 + uu)*BSP + k);
                    #pragma unroll
                    for (int ss=0;ss<SPT;ss++){
                        fma2(acc[uu][q][ss], h0[ss], bv.x);
                        fma2(acc[uu][q][ss], h1[ss], bv.y);
                    }
                }
        }
        float pre[3][4][SPT];
        #pragma unroll
        for (int uu=0;uu<3;uu++)
            #pragma unroll
            for (int q=0;q<4;q++)
                #pragma unroll
                for (int ss=0;ss<SPT;ss++) pre[uu][q][ss] = lohi(acc[uu][q][ss]) + gxr[uu][q][ss];

        CL_ARRIVE();
        CL_WAIT();

        float hv[3][SPT];
        #pragma unroll
        for (int uu=0;uu<3;uu++)
            #pragma unroll
            for (int ss=0;ss<SPT;ss++){
                float iv = sigm(pre[uu][0][ss]);
                float fv = sigm(pre[uu][1][ss]);
                float gv = tanhf(pre[uu][2][ss]);
                float ov = sigm(pre[uu][3][ss]);
                float cc = fv*c[uu][ss] + iv*gv;
                c[uu][ss] = cc;
                hv[uu][ss] = ov*tanhf(cc);
            }
        #pragma unroll
        for (int ss=0;ss<SPT;ss++){
            int sl = sgrp + 32*ss;
            #pragma unroll
            for (int uu=0;uu<3;uu++){
                uint32_t la = hs_base + (uint32_t)(sl*HSP + jsl + rgrp*3 + uu)*4u;
                float v = hv[uu][ss];
                Hs[sl*HSP + jsl + rgrp*3 + uu] = v;
                #pragma unroll
                for (int r=0;r<4;r++){
                    if (r == (int)rank) continue;
                    uint32_t da; asm("mapa.shared::cluster.u32 %0,%1,%2;":"=r"(da):"r"(la),"r"(r));
                    asm volatile("st.shared::cluster.f32 [%0],%1;"::"r"(da),"f"(v));
                }
            }
        }
        CL_ARRIVE();
        if (mode==0 || mode==1){
            #pragma unroll
            for (int ss=0;ss<SPT;ss++){
                int s = sbase + sgrp + 32*ss;
                float* op = outp + ((size_t)s*T + tt)*384 + (mode==1?192:0) + jsl + rgrp*3;
                op[0]=hv[0][ss]; op[1]=hv[1][ss]; op[2]=hv[2][ss];
            }
        } else if (step==T-1){
            #pragma unroll
            for (int ss=0;ss<SPT;ss++){
                int s = sbase + sgrp + 32*ss;
                float* op = outp + (size_t)s*384 + jsl + rgrp*3;
                op[0]=hv[0][ss]; op[1]=hv[1][ss]; op[2]=hv[2][ss];
            }
        }
        CL_WAIT();
    }
}

// ---- layer1 bwd @ t=31 only (h0=c0=0) ----
__global__ void bwd1_last(const float* __restrict__ gxb, float* __restrict__ h2)
{
    int n = blockIdx.x, j = threadIdx.x;
    const float* g = gxb + (size_t)n*G;
    float iv = sigm(g[j]);
    float gv = tanhf(g[2*H+j]);
    float ov = sigm(g[3*H+j]);
    float cc = iv*gv;
    h2[(size_t)n*384 + 192 + j] = ov*tanhf(cc);
}

// ---- dynamic network ----
__global__ void dyn_scalars(const float* __restrict__ x, const float* __restrict__ theta,
                            int* __restrict__ pid, int* __restrict__ off)
{
    int n = blockIdx.x*blockDim.x + threadIdx.x;
    if (n >= NS) return;
    float th  = theta[n];
    float x30 = x[((size_t)n*T + 30)*NF];
    float x31 = x[((size_t)n*T + 31)*NF];
    int p0 = (x30 > th) ? 1 : ((x30 < -th) ? -1 : 0);
    int p1 = (x31 > th) ? 1 : ((x31 < -th) ? -1 : 0);
    pid[n] = (p0+1)*3 + (p1+1);
    off[n] = (p1+1)*3;
}

__global__ __launch_bounds__(256,1)
void dyn_beta(const float* __restrict__ PP, const int* __restrict__ pid,
              const int* __restrict__ off, float* __restrict__ BetaT,
              float* __restrict__ t3)
{
    __shared__ float s_raw[1024];
    __shared__ float s_adj[1024*3];
    __shared__ float s_red[256];
    const int y = blockIdx.x, tid = threadIdx.x;
    const int offy = off[y];
    for (int x=tid; x<NS; x+=256){
        size_t base = ((size_t)x*NS + y)*81 + (size_t)pid[x]*9 + offy;
        float a0=PP[base], a1=PP[base+1], a2=PP[base+2];
        s_adj[x*3+0]=a0; s_adj[x*3+1]=a1; s_adj[x*3+2]=a2;
        float nr = sqrtf(a0*a0+a1*a1+a2*a2);
        s_raw[x] = (nr > 0.38f) ? nr : 0.f;
    }
    __syncthreads();
    float lm = -1e30f;
    for (int x=tid; x<NS; x+=256) lm = fmaxf(lm, s_raw[x]);
    s_red[tid]=lm; __syncthreads();
    for (int o=128;o>0;o>>=1){ if(tid<o) s_red[tid]=fmaxf(s_red[tid],s_red[tid+o]); __syncthreads(); }
    const float mx = s_red[0];
    __syncthreads();
    float ls = 0.f;
    for (int x=tid; x<NS; x+=256){ float e=expf(s_raw[x]-mx); s_raw[x]=e; ls+=e; }
    s_red[tid]=ls; __syncthreads();
    for (int o=128;o>0;o>>=1){ if(tid<o) s_red[tid]+=s_red[tid+o]; __syncthreads(); }
    const float inv = 1.f/s_red[0];
    __syncthreads();
    float t0=0.f,t1=0.f,t2=0.f;
    for (int x=tid; x<NS; x+=256){
        float b = s_raw[x]*inv;
        BetaT[(size_t)y*NS + x] = b;
        t0 += b*s_adj[x*3+0]; t1 += b*s_adj[x*3+1]; t2 += b*s_adj[x*3+2];
    }
    s_red[tid]=t0; __syncthreads();
    for (int o=128;o>0;o>>=1){ if(tid<o) s_red[tid]+=s_red[tid+o]; __syncthreads(); }
    if(tid==0) t3[y*3+0]=s_red[0];
    __syncthreads();
    s_red[tid]=t1; __syncthreads();
    for (int o=128;o>0;o>>=1){ if(tid<o) s_red[tid]+=s_red[tid+o]; __syncthreads(); }
    if(tid==0) t3[y*3+1]=s_red[0];
    __syncthreads();
    s_red[tid]=t2; __syncthreads();
    for (int o=128;o>0;o>>=1){ if(tid<o) s_red[tid]+=s_red[tid+o]; __syncthreads(); }
    if(tid==0) t3[y*3+2]=s_red[0];
}

__global__ void agg_extra(const float* __restrict__ t3, const float* __restrict__ Wa,
                          const float* __restrict__ b, float* __restrict__ E)
{
    int y = blockIdx.x, u = threadIdx.x;
    float v = b[u] + t3[y*3+0]*Wa[u] + t3[y*3+1]*Wa[128+u] + t3[y*3+2]*Wa[256+u];
    E[(size_t)y*128 + u] = v;
}

__global__ void out_kernel(const float* __restrict__ nfeat, const float* __restrict__ n1,
                           const float* __restrict__ n2, const float* __restrict__ W,
                           const float* __restrict__ b, float* __restrict__ out)
{
    int warp = (blockIdx.x*blockDim.x + threadIdx.x)>>5;
    int lane = threadIdx.x & 31;
    if (warp >= NS*2) return;
    int n = warp>>1, o = warp&1;
    float s = 0.f;
    for (int k=lane;k<384;k+=32) s += nfeat[(size_t)n*384+k]*W[k*2+o];
    for (int k=lane;k<128;k+=32) s += n1[(size_t)n*128+k]*W[(384+k)*2+o];
    for (int k=lane;k<128;k+=32) s += n2[(size_t)n*128+k]*W[(512+k)*2+o];
    #pragma unroll
    for (int m=16;m>0;m>>=1) s += __shfl_xor_sync(0xffffffffu, s, m);
    if (lane==0) out[warp] = tanhf(s + b[o]);
}

extern "C" void kernel_launch(void* const* d_in, const int* in_sizes, int n_in,
                              void* d_out, int out_size)
{
    const float* x     = (const float*)d_in[0];
    const float* theta = (const float*)d_in[1];
    const float* PP    = (const float*)d_in[2];
    const float* Wih0  = (const float*)d_in[3];
    const float* Whh0  = (const float*)d_in[4];
    const float* bih0  = (const float*)d_in[5];
    const float* bhh0  = (const float*)d_in[6];
    const float* Wih1  = (const float*)d_in[7];
    const float* Whh1  = (const float*)d_in[8];
    const float* bih1  = (const float*)d_in[9];
    const float* bhh1  = (const float*)d_in[10];
    const float* Wagg1 = (const float*)d_in[11];
    const float* bagg1 = (const float*)d_in[12];
    const float* Wagg2 = (const float*)d_in[13];
    const float* bagg2 = (const float*)d_in[14];
    const float* Wout  = (const float*)d_in[15];
    const float* bout  = (const float*)d_in[16];
    float* out = (float*)d_out;

    float *p_gx0, *p_gx1, *p_gx1b, *p_h1, *p_h2, *p_BetaT, *p_t3, *p_M, *p_E, *p_n1, *p_n2;
    int *p_pid, *p_off;
    cudaGetSymbolAddress((void**)&p_gx0,  g_gx0);
    cudaGetSymbolAddress((void**)&p_gx1,  g_gx1);
    cudaGetSymbolAddress((void**)&p_gx1b, g_gx1b);
    cudaGetSymbolAddress((void**)&p_h1,   g_h1);
    cudaGetSymbolAddress((void**)&p_h2,   g_h2);
    cudaGetSymbolAddress((void**)&p_BetaT,g_BetaT);
    cudaGetSymbolAddress((void**)&p_t3,   g_t3);
    cudaGetSymbolAddress((void**)&p_pid,  g_pid);
    cudaGetSymbolAddress((void**)&p_off,  g_off);
    cudaGetSymbolAddress((void**)&p_M,    g_M);
    cudaGetSymbolAddress((void**)&p_E,    g_E);
    cudaGetSymbolAddress((void**)&p_n1,   g_n1);
    cudaGetSymbolAddress((void**)&p_n2,   g_n2);

    const int SM64 = (192*196 + 64*202)*4;   // 202240 B
    const int SM32 = (192*196 + 32*202)*4;   // 176384 B
    const int CSH  = 128*132*4;              // 67584 B
    cudaFuncSetAttribute(lstm_cluster<64>, cudaFuncAttributeMaxDynamicSharedMemorySize, SM64);
    cudaFuncSetAttribute(lstm_cluster<32>, cudaFuncAttributeMaxDynamicSharedMemorySize, SM32);
    cudaFuncSetAttribute(gemm_nt128T, cudaFuncAttributeMaxDynamicSharedMemorySize, CSH);

    // #1-2: layer0 gx, time-major, both dirs
    for (int d=0; d<2; d++){
        gemm_nt128T<<<dim3(256,6), 256, CSH>>>(x, NF, Wih0 + (size_t)d*G*NF, NF,
                                               p_gx0 + (size_t)d*NS*T*G, NF,
                                               bih0 + d*G, bhh0 + d*G);
    }
    // #3: tiny independent kernel (keeps profile slot alignment)
    dyn_scalars<<<4, 256>>>(x, theta, p_pid, p_off);

    // #4: layer0 recurrence, fwd+bwd — target of ncu -s 5 -c 1
    lstm_cluster<64><<<dim3(64,2), 512, SM64>>>(p_gx0, Whh0, p_h1, 0);

    // #5: dynamic network main
    dyn_beta<<<NS, 256>>>(PP, p_pid, p_off, p_BetaT, p_t3);

    // #6: layer1 fwd gx, time-major
    gemm_nt128T<<<dim3(256,6), 256, CSH>>>(p_h1, 384, Wih1, 384, p_gx1, 384,
                                           bih1, bhh1);
    // #7: layer1 bwd gx at t=31 only ([s][j] layout)
    gemm_nt128<<<dim3(8,6), 256>>>(p_h1 + 31*384, T*384, Wih1 + (size_t)G*384, 384,
                                   p_gx1b, G, 384, bih1 + G, bhh1 + G);

    // #8-9: layer1 recurrence fwd; bwd single step
    lstm_cluster<32><<<dim3(128,1), 512, SM32>>>(p_gx1, Whh1, p_h2, 2);
    bwd1_last<<<NS, H>>>(p_gx1b, p_h2);

    // #10-12: agg layer 1
    agg_extra<<<NS, 128>>>(p_t3, Wagg1 + (size_t)384*128, bagg1, p_E);
    gemm_nn64<<<dim3(16,2), 256>>>(p_h2, 384, Wagg1, 128, p_M, 128, 384, (const float*)0);
    gemm_nn64<<<dim3(16,2), 256>>>(p_BetaT, NS, p_M, 128, p_n1, 128, NS, p_E);

    // #13-15: agg layer 2
    gemm_nn64<<<dim3(16,2), 256>>>(p_n1, 128, Wagg2, 128, p_M, 128, 128, (const float*)0);
    agg_extra<<<NS, 128>>>(p_t3, Wagg2 + (size_t)128*128, bagg2, p_E);
    gemm_nn64<<<dim3(16,2), 256>>>(p_BetaT, NS, p_M, 128, p_n2, 128, NS, p_E);

    // #16: output
    out_kernel<<<256, 256>>>(p_h2, p_n1, p_n2, Wout, bout, out);
}